// round 4
// baseline (speedup 1.0000x reference)
#include <cuda_runtime.h>
#include <math.h>
#include <stddef.h>

#define T_STEPS 256
#define BATCH   64
#define DIN     512
#define HID     1024
#define DOUT    512
#define G4      (4*HID)          /* 4096 */
#define MB      (T_STEPS*BATCH)  /* 16384 */
#define NCTA    128

// ---------------- scratch (device globals; no runtime allocation) ----------
__device__ __align__(16) float g_GX[(size_t)MB * G4];     // 256 MB: inputs@Wx0+b0
__device__ __align__(16) float g_H1[(size_t)MB * HID];    //  64 MB: h1 for all t
__device__ __align__(16) float g_h0T[2][HID][BATCH];      // transposed h0, double-buffered
__device__ __align__(16) float g_h1T[2][HID][BATCH];      // transposed h1, double-buffered
__device__ unsigned g_bar_count = 0;
__device__ unsigned g_bar_gen   = 0;

// ---------------- software grid barrier (all 128 CTAs co-resident) ---------
__device__ __forceinline__ void grid_barrier() {
    __syncthreads();
    __threadfence();
    if (threadIdx.x == 0) {
        unsigned gen = *(volatile unsigned*)&g_bar_gen;
        if (atomicAdd(&g_bar_count, 1u) == NCTA - 1) {
            *(volatile unsigned*)&g_bar_count = 0;
            __threadfence();
            *(volatile unsigned*)&g_bar_gen = gen + 1;
        } else {
            while (*(volatile unsigned*)&g_bar_gen == gen) { __nanosleep(20); }
        }
    }
    __syncthreads();
    __threadfence();
}

__device__ __forceinline__ float sigm(float x) { return 1.0f / (1.0f + expf(-x)); }

// ---------------- persistent recurrence kernel ------------------------------
// CTA c owns h-columns [8c, 8c+8). Thread layout:
//   gi = tid & 31 : gate g = gi>>3 (0..3), local hcol hc = gi&7
//   ty = tid >> 5 : rows r0 = ty*8 .. +8   (warp = fixed rows, 32 gate-cols)
__global__ __launch_bounds__(256) void lstm_persistent(
        const float* __restrict__ Wh0,
        const float* __restrict__ Wx1,
        const float* __restrict__ Wh1,
        const float* __restrict__ b1,
        float* __restrict__ out) {
    __shared__ float sG[32][65];    // gate tile (padded: conflict-free)
    __shared__ float sc0[8][64];    // persistent c-state, layer 0 (own cols)
    __shared__ float sc1[8][64];    // persistent c-state, layer 1

    const int tid = threadIdx.x;
    const int hc0 = blockIdx.x * 8;
    const int gi  = tid & 31;
    const int gcol = (gi >> 3) * HID + hc0 + (gi & 7);   // global gate column
    const int ty  = tid >> 5;
    const int r0  = ty * 8;

    // ---- init state ----
    for (int e = tid; e < 512; e += 256) {
        const int r = e & 63, hc = e >> 6;
        sc0[hc][r] = 0.f;
        sc1[hc][r] = 0.f;
        g_h0T[0][hc0 + hc][r] = 0.f;
        g_h1T[0][hc0 + hc][r] = 0.f;
    }
    grid_barrier();

    for (int t = 0; t < T_STEPS; t++) {
        const int rbuf = t & 1;
        const int wbuf = rbuf ^ 1;

        // ======== phase A: G0 = GX[t] + h0 @ Wh0 ========
        float acc[8];
        {
            const float* gx = g_GX + ((size_t)t * BATCH) * G4 + gcol;
#pragma unroll
            for (int i = 0; i < 8; i++) acc[i] = gx[(size_t)(r0 + i) * G4];
            const float* w = Wh0 + gcol;
#pragma unroll 4
            for (int k = 0; k < HID; k++) {
                const float wv = w[(size_t)k * G4];
                const float4 ha = *(const float4*)&g_h0T[rbuf][k][r0];
                const float4 hb = *(const float4*)&g_h0T[rbuf][k][r0 + 4];
                acc[0] += ha.x * wv; acc[1] += ha.y * wv;
                acc[2] += ha.z * wv; acc[3] += ha.w * wv;
                acc[4] += hb.x * wv; acc[5] += hb.y * wv;
                acc[6] += hb.z * wv; acc[7] += hb.w * wv;
            }
        }
#pragma unroll
        for (int i = 0; i < 8; i++) sG[gi][r0 + i] = acc[i];
        __syncthreads();

        // activation L0 -> h0T[wbuf]
        for (int e = tid; e < 512; e += 256) {
            const int r = e & 63, hc = e >> 6;
            const float i_ = sigm(sG[hc][r]);
            const float f_ = sigm(sG[8 + hc][r]);
            const float cg = tanhf(sG[16 + hc][r]);
            const float o_ = sigm(sG[24 + hc][r]);
            const float cn = f_ * sc0[hc][r] + i_ * cg;
            sc0[hc][r] = cn;
            g_h0T[wbuf][hc0 + hc][r] = o_ * tanhf(cn);
        }
        grid_barrier();   // all of new h0 visible everywhere

        // ======== phase B: G1 = b1 + h0new @ Wx1 + h1old @ Wh1 ========
        {
            const float bias = b1[gcol];
#pragma unroll
            for (int i = 0; i < 8; i++) acc[i] = bias;
            const float* w1 = Wx1 + gcol;
            const float* w2 = Wh1 + gcol;
#pragma unroll 2
            for (int k = 0; k < HID; k++) {
                const float wa = w1[(size_t)k * G4];
                const float wc = w2[(size_t)k * G4];
                const float4 xa = *(const float4*)&g_h0T[wbuf][k][r0];
                const float4 xb = *(const float4*)&g_h0T[wbuf][k][r0 + 4];
                const float4 ya = *(const float4*)&g_h1T[rbuf][k][r0];
                const float4 yb = *(const float4*)&g_h1T[rbuf][k][r0 + 4];
                acc[0] += xa.x * wa + ya.x * wc;
                acc[1] += xa.y * wa + ya.y * wc;
                acc[2] += xa.z * wa + ya.z * wc;
                acc[3] += xa.w * wa + ya.w * wc;
                acc[4] += xb.x * wa + yb.x * wc;
                acc[5] += xb.y * wa + yb.y * wc;
                acc[6] += xb.z * wa + yb.z * wc;
                acc[7] += xb.w * wa + yb.w * wc;
            }
        }
#pragma unroll
        for (int i = 0; i < 8; i++) sG[gi][r0 + i] = acc[i];
        __syncthreads();

        // activation L1 -> h1T[wbuf], g_H1[t]
        for (int e = tid; e < 512; e += 256) {
            const int r = e & 63, hc = e >> 6;
            const float i_ = sigm(sG[hc][r]);
            const float f_ = sigm(sG[8 + hc][r]);
            const float cg = tanhf(sG[16 + hc][r]);
            const float o_ = sigm(sG[24 + hc][r]);
            const float cn = f_ * sc1[hc][r] + i_ * cg;
            const float h  = o_ * tanhf(cn);
            sc1[hc][r] = cn;
            g_h1T[wbuf][hc0 + hc][r] = h;
            g_H1[((size_t)t * BATCH + r) * HID + hc0 + hc] = h;
        }
        grid_barrier();   // all of new h1 visible before next step reads it
    }

    // ---- tail: final_h, final_c for layer 1 ----
    const int fbuf = ((T_STEPS - 1) & 1) ^ 1;   // wbuf of the last step
    for (int e = tid; e < 512; e += 256) {
        const int r = e & 63, hc = e >> 6;
        const size_t off = (size_t)MB * DOUT;
        out[off + (size_t)r * HID + hc0 + hc]              = g_h1T[fbuf][hc0 + hc][r];
        out[off + (size_t)BATCH * HID + (size_t)r * HID + hc0 + hc] = sc1[hc][r];
    }
}

// ---------------- big GEMM: C[M,N] = A[M,K] @ B[K,N] + bias[N] -------------
// 64x64 tile, BK=8, 256 threads, 4x4 per thread.
__global__ __launch_bounds__(256) void gemm_bias_kernel(
        const float* __restrict__ A,
        const float* __restrict__ B,
        const float* __restrict__ bias,
        float* __restrict__ C,
        int M, int N, int K) {
    __shared__ float As[8][72];
    __shared__ float Bs[8][64];
    const int tid = threadIdx.x;
    const int colBase = blockIdx.x * 64;
    const int rowBase = blockIdx.y * 64;
    const int tx = tid & 15, ty = tid >> 4;

    float acc[4][4] = {};

    const int ar  = tid >> 2;
    const int akp = (tid & 3) * 2;
    const int bk  = tid >> 5;
    const int bc  = (tid & 31) * 2;

    const float* Aptr = A + (size_t)(rowBase + ar) * K + akp;
    const float* Bptr = B + (size_t)bk * N + colBase + bc;

    for (int k0 = 0; k0 < K; k0 += 8) {
        float2 av = *(const float2*)(Aptr + k0);
        float2 bv = *(const float2*)(Bptr + (size_t)k0 * N);
        __syncthreads();
        As[akp][ar]     = av.x;
        As[akp + 1][ar] = av.y;
        *(float2*)&Bs[bk][bc] = bv;
        __syncthreads();
#pragma unroll
        for (int kk = 0; kk < 8; kk++) {
            float a[4], b[4];
            *(float4*)a = *(const float4*)&As[kk][ty * 4];
            *(float4*)b = *(const float4*)&Bs[kk][tx * 4];
#pragma unroll
            for (int i = 0; i < 4; i++)
#pragma unroll
                for (int j = 0; j < 4; j++)
                    acc[i][j] += a[i] * b[j];
        }
    }
#pragma unroll
    for (int i = 0; i < 4; i++) {
        const int r = rowBase + ty * 4 + i;
#pragma unroll
        for (int j = 0; j < 4; j++) {
            const int c = colBase + tx * 4 + j;
            C[(size_t)r * N + c] = acc[i][j] + bias[c];
        }
    }
}

// ---------------- launch ----------------------------------------------------
extern "C" void kernel_launch(void* const* d_in, const int* in_sizes, int n_in,
                              void* d_out, int out_size) {
    const float* inputs = (const float*)d_in[0];
    const float* Wx0    = (const float*)d_in[1];
    const float* Wh0    = (const float*)d_in[2];
    const float* b0     = (const float*)d_in[3];
    const float* Wx1    = (const float*)d_in[4];
    const float* Wh1    = (const float*)d_in[5];
    const float* b1     = (const float*)d_in[6];
    const float* Wout   = (const float*)d_in[7];
    const float* bout   = (const float*)d_in[8];
    float* out = (float*)d_out;

    float *pGX, *pH1;
    cudaGetSymbolAddress((void**)&pGX, g_GX);
    cudaGetSymbolAddress((void**)&pH1, g_H1);

    // 1) precompute GX = inputs @ Wx0 + b0   [16384 x 4096]
    gemm_bias_kernel<<<dim3(G4 / 64, MB / 64), 256>>>(inputs, Wx0, b0, pGX,
                                                      MB, G4, DIN);

    // 2) full 256-step recurrence in ONE persistent kernel (incl. state init + tail)
    lstm_persistent<<<NCTA, 256>>>(Wh0, Wx1, Wh1, b1, out);

    // 3) outs = H1_all @ Wout + bout  -> d_out[0 : 16384*512)
    gemm_bias_kernel<<<dim3(DOUT / 64, MB / 64), 256>>>(pH1, Wout, bout, out,
                                                        MB, DOUT, HID);
}

// round 6
// speedup vs baseline: 1.0888x; 1.0888x over previous
#include <cuda_runtime.h>
#include <math.h>
#include <stddef.h>

#define T_STEPS 256
#define BATCH   64
#define DIN     512
#define HID     1024
#define DOUT    512
#define G4      (4*HID)          /* 4096 */
#define MB      (T_STEPS*BATCH)  /* 16384 */
#define NCTA    128
#define K4      (HID/4)          /* 256 k-groups */

// ---------------- scratch (device globals; no runtime allocation) ----------
__device__ __align__(16) float g_GX[(size_t)MB * G4];     // 256 MB: inputs@Wx0+b0
__device__ __align__(16) float g_H1[(size_t)MB * HID];    //  64 MB: h1 for all t
__device__ __align__(16) float g_h0T[2][HID][BATCH];      // transposed h0, double-buffered
__device__ __align__(16) float g_h1T[2][HID][BATCH];      // transposed h1, double-buffered
// packed weights: P[((cta*K4 + k4)*32 + gi)*4 + j] = W[(k4*4+j)*G4 + col(cta,gi)]
__device__ __align__(16) float g_pWh0[(size_t)NCTA * HID * 32];
__device__ __align__(16) float g_pWx1[(size_t)NCTA * HID * 32];
__device__ __align__(16) float g_pWh1[(size_t)NCTA * HID * 32];
__device__ unsigned g_bar_count = 0;
__device__ unsigned g_bar_gen   = 0;

// ---------------- software grid barrier (all 128 CTAs co-resident) ---------
__device__ __forceinline__ void grid_barrier() {
    __syncthreads();
    __threadfence();
    if (threadIdx.x == 0) {
        unsigned gen = *(volatile unsigned*)&g_bar_gen;
        if (atomicAdd(&g_bar_count, 1u) == NCTA - 1) {
            *(volatile unsigned*)&g_bar_count = 0;
            __threadfence();
            *(volatile unsigned*)&g_bar_gen = gen + 1;
        } else {
            while (*(volatile unsigned*)&g_bar_gen == gen) { __nanosleep(20); }
        }
    }
    __syncthreads();
    __threadfence();
}

__device__ __forceinline__ float sigm(float x) { return 1.0f / (1.0f + expf(-x)); }

// ---------------- weight packing: coalesced per-CTA k-major blocks ---------
__global__ __launch_bounds__(256) void pack_weights(const float* __restrict__ W,
                                                    float* __restrict__ P) {
    const size_t total = (size_t)NCTA * HID * 32;
    for (size_t idx = (size_t)blockIdx.x * blockDim.x + threadIdx.x;
         idx < total; idx += (size_t)gridDim.x * blockDim.x) {
        const int cta = (int)(idx >> 15);          // /32768
        const int rem = (int)(idx & 32767);
        const int k4  = rem >> 7;
        const int gi  = (rem >> 2) & 31;
        const int j   = rem & 3;
        const int k   = k4 * 4 + j;
        const int col = (gi >> 3) * HID + cta * 8 + (gi & 7);
        P[idx] = W[(size_t)k * G4 + col];
    }
}

// ---------------- persistent recurrence kernel ------------------------------
// CTA c owns h-columns [8c, 8c+8). gi = tid&31: gate (gi>>3), hcol (gi&7).
// ty = tid>>5: batch rows r0 = ty*8 .. +8.
__global__ __launch_bounds__(256) void lstm_persistent(
        const float* __restrict__ b1,
        float* __restrict__ out) {
    __shared__ float sG[32][65];    // gate tile (padded)
    __shared__ float sc0[8][64];    // persistent c-state, layer 0
    __shared__ float sc1[8][64];    // persistent c-state, layer 1

    const int tid = threadIdx.x;
    const int hc0 = blockIdx.x * 8;
    const int gi  = tid & 31;
    const int gcol = (gi >> 3) * HID + hc0 + (gi & 7);
    const int ty  = tid >> 5;
    const int r0  = ty * 8;

    const float* wp0 = g_pWh0 + (size_t)blockIdx.x * (HID * 32) + gi * 4;
    const float* wp1 = g_pWx1 + (size_t)blockIdx.x * (HID * 32) + gi * 4;
    const float* wp2 = g_pWh1 + (size_t)blockIdx.x * (HID * 32) + gi * 4;

    // ---- init state ----
    for (int e = tid; e < 512; e += 256) {
        const int r = e & 63, hc = e >> 6;
        sc0[hc][r] = 0.f;
        sc1[hc][r] = 0.f;
        g_h0T[0][hc0 + hc][r] = 0.f;
        g_h1T[0][hc0 + hc][r] = 0.f;
    }
    grid_barrier();

    for (int t = 0; t < T_STEPS; t++) {
        const int rbuf = t & 1;
        const int wbuf = rbuf ^ 1;

        // ======== phase A: G0 = GX[t] + h0 @ Wh0 ========
        float acc[8];
        {
            const float* gx = g_GX + ((size_t)t * BATCH) * G4 + gcol;
#pragma unroll
            for (int i = 0; i < 8; i++) acc[i] = gx[(size_t)(r0 + i) * G4];
            const float* hbase = &g_h0T[rbuf][0][0];
#pragma unroll 2
            for (int k4 = 0; k4 < K4; k4++) {
                const float4 wv = *(const float4*)(wp0 + (size_t)k4 * 128);
#pragma unroll
                for (int j = 0; j < 4; j++) {
                    const float w = j == 0 ? wv.x : j == 1 ? wv.y : j == 2 ? wv.z : wv.w;
                    const float* hk = hbase + (size_t)(k4 * 4 + j) * BATCH + r0;
                    const float4 ha = *(const float4*)hk;
                    const float4 hb = *(const float4*)(hk + 4);
                    acc[0] += ha.x * w; acc[1] += ha.y * w;
                    acc[2] += ha.z * w; acc[3] += ha.w * w;
                    acc[4] += hb.x * w; acc[5] += hb.y * w;
                    acc[6] += hb.z * w; acc[7] += hb.w * w;
                }
            }
        }
#pragma unroll
        for (int i = 0; i < 8; i++) sG[gi][r0 + i] = acc[i];
        __syncthreads();

        // activation L0 -> h0T[wbuf]
        for (int e = tid; e < 512; e += 256) {
            const int r = e & 63, hc = e >> 6;
            const float i_ = sigm(sG[hc][r]);
            const float f_ = sigm(sG[8 + hc][r]);
            const float cg = tanhf(sG[16 + hc][r]);
            const float o_ = sigm(sG[24 + hc][r]);
            const float cn = f_ * sc0[hc][r] + i_ * cg;
            sc0[hc][r] = cn;
            g_h0T[wbuf][hc0 + hc][r] = o_ * tanhf(cn);
        }
        grid_barrier();   // all of new h0 visible everywhere

        // ======== phase B: G1 = b1 + h0new @ Wx1 + h1old @ Wh1 ========
        {
            const float bias = b1[gcol];
#pragma unroll
            for (int i = 0; i < 8; i++) acc[i] = bias;
            const float* xbase = &g_h0T[wbuf][0][0];
            const float* ybase = &g_h1T[rbuf][0][0];
#pragma unroll 2
            for (int k4 = 0; k4 < K4; k4++) {
                const float4 wa4 = *(const float4*)(wp1 + (size_t)k4 * 128);
                const float4 wc4 = *(const float4*)(wp2 + (size_t)k4 * 128);
#pragma unroll
                for (int j = 0; j < 4; j++) {
                    const float wa = j == 0 ? wa4.x : j == 1 ? wa4.y : j == 2 ? wa4.z : wa4.w;
                    const float wc = j == 0 ? wc4.x : j == 1 ? wc4.y : j == 2 ? wc4.z : wc4.w;
                    const size_t ko = (size_t)(k4 * 4 + j) * BATCH + r0;
                    const float4 xa = *(const float4*)(xbase + ko);
                    const float4 xb = *(const float4*)(xbase + ko + 4);
                    const float4 ya = *(const float4*)(ybase + ko);
                    const float4 yb = *(const float4*)(ybase + ko + 4);
                    acc[0] += xa.x * wa + ya.x * wc;
                    acc[1] += xa.y * wa + ya.y * wc;
                    acc[2] += xa.z * wa + ya.z * wc;
                    acc[3] += xa.w * wa + ya.w * wc;
                    acc[4] += xb.x * wa + yb.x * wc;
                    acc[5] += xb.y * wa + yb.y * wc;
                    acc[6] += xb.z * wa + yb.z * wc;
                    acc[7] += xb.w * wa + yb.w * wc;
                }
            }
        }
#pragma unroll
        for (int i = 0; i < 8; i++) sG[gi][r0 + i] = acc[i];
        __syncthreads();

        // activation L1 -> h1T[wbuf], g_H1[t]
        for (int e = tid; e < 512; e += 256) {
            const int r = e & 63, hc = e >> 6;
            const float i_ = sigm(sG[hc][r]);
            const float f_ = sigm(sG[8 + hc][r]);
            const float cg = tanhf(sG[16 + hc][r]);
            const float o_ = sigm(sG[24 + hc][r]);
            const float cn = f_ * sc1[hc][r] + i_ * cg;
            const float h  = o_ * tanhf(cn);
            sc1[hc][r] = cn;
            g_h1T[wbuf][hc0 + hc][r] = h;
            g_H1[((size_t)t * BATCH + r) * HID + hc0 + hc] = h;
        }
        grid_barrier();   // all of new h1 visible before next step reads it
    }

    // ---- tail: final_h, final_c for layer 1 ----
    const int fbuf = ((T_STEPS - 1) & 1) ^ 1;
    for (int e = tid; e < 512; e += 256) {
        const int r = e & 63, hc = e >> 6;
        const size_t off = (size_t)MB * DOUT;
        out[off + (size_t)r * HID + hc0 + hc]                       = g_h1T[fbuf][hc0 + hc][r];
        out[off + (size_t)BATCH * HID + (size_t)r * HID + hc0 + hc] = sc1[hc][r];
    }
}

// ---------------- big GEMM: C[M,N] = A[M,K] @ B[K,N] + bias[N] -------------
__global__ __launch_bounds__(256) void gemm_bias_kernel(
        const float* __restrict__ A,
        const float* __restrict__ B,
        const float* __restrict__ bias,
        float* __restrict__ C,
        int M, int N, int K) {
    __shared__ float As[8][72];
    __shared__ float Bs[8][64];
    const int tid = threadIdx.x;
    const int colBase = blockIdx.x * 64;
    const int rowBase = blockIdx.y * 64;
    const int tx = tid & 15, ty = tid >> 4;

    float acc[4][4] = {};

    const int ar  = tid >> 2;
    const int akp = (tid & 3) * 2;
    const int bk  = tid >> 5;
    const int bc  = (tid & 31) * 2;

    const float* Aptr = A + (size_t)(rowBase + ar) * K + akp;
    const float* Bptr = B + (size_t)bk * N + colBase + bc;

    for (int k0 = 0; k0 < K; k0 += 8) {
        float2 av = *(const float2*)(Aptr + k0);
        float2 bv = *(const float2*)(Bptr + (size_t)k0 * N);
        __syncthreads();
        As[akp][ar]     = av.x;
        As[akp + 1][ar] = av.y;
        *(float2*)&Bs[bk][bc] = bv;
        __syncthreads();
#pragma unroll
        for (int kk = 0; kk < 8; kk++) {
            float a[4], b[4];
            *(float4*)a = *(const float4*)&As[kk][ty * 4];
            *(float4*)b = *(const float4*)&Bs[kk][tx * 4];
#pragma unroll
            for (int i = 0; i < 4; i++)
#pragma unroll
                for (int j = 0; j < 4; j++)
                    acc[i][j] += a[i] * b[j];
        }
    }
#pragma unroll
    for (int i = 0; i < 4; i++) {
        const int r = rowBase + ty * 4 + i;
#pragma unroll
        for (int j = 0; j < 4; j++) {
            const int c = colBase + tx * 4 + j;
            C[(size_t)r * N + c] = acc[i][j] + bias[c];
        }
    }
}

// ---------------- launch ----------------------------------------------------
extern "C" void kernel_launch(void* const* d_in, const int* in_sizes, int n_in,
                              void* d_out, int out_size) {
    const float* inputs = (const float*)d_in[0];
    const float* Wx0    = (const float*)d_in[1];
    const float* Wh0    = (const float*)d_in[2];
    const float* b0     = (const float*)d_in[3];
    const float* Wx1    = (const float*)d_in[4];
    const float* Wh1    = (const float*)d_in[5];
    const float* b1     = (const float*)d_in[6];
    const float* Wout   = (const float*)d_in[7];
    const float* bout   = (const float*)d_in[8];
    float* out = (float*)d_out;

    float *pGX, *pH1, *pp0, *pp1, *pp2;
    cudaGetSymbolAddress((void**)&pGX, g_GX);
    cudaGetSymbolAddress((void**)&pH1, g_H1);
    cudaGetSymbolAddress((void**)&pp0, g_pWh0);
    cudaGetSymbolAddress((void**)&pp1, g_pWx1);
    cudaGetSymbolAddress((void**)&pp2, g_pWh1);

    // 0) pack recurrent weights into per-CTA coalesced blocks
    pack_weights<<<512, 256>>>(Wh0, pp0);
    pack_weights<<<512, 256>>>(Wx1, pp1);
    pack_weights<<<512, 256>>>(Wh1, pp2);

    // 1) precompute GX = inputs @ Wx0 + b0   [16384 x 4096]
    gemm_bias_kernel<<<dim3(G4 / 64, MB / 64), 256>>>(inputs, Wx0, b0, pGX,
                                                      MB, G4, DIN);

    // 2) full 256-step recurrence in ONE persistent kernel
    lstm_persistent<<<NCTA, 256>>>(b1, out);

    // 3) outs = H1_all @ Wout + bout  -> d_out[0 : 16384*512)
    gemm_bias_kernel<<<dim3(DOUT / 64, MB / 64), 256>>>(pH1, Wout, bout, out,
                                                        MB, DOUT, HID);
}

// round 7
// speedup vs baseline: 7.3997x; 6.7962x over previous
#include <cuda_runtime.h>
#include <cuda_bf16.h>
#include <math.h>
#include <stdint.h>
#include <stddef.h>

#define T_STEPS 256
#define BATCH   64
#define DIN     512
#define HID     1024
#define DOUT    512
#define G4      (4*HID)          /* 4096 */
#define MB      (T_STEPS*BATCH)  /* 16384 */
#define NCTA    128
#define KC      64               /* k-chunk */
#define KROW    72               /* padded bf16 elems per smem row (anti-conflict) */

typedef __nv_bfloat16 bf16;

// ---------------- scratch (device globals; no runtime allocation) ----------
__device__ __align__(16) float g_GX[(size_t)MB * G4];     // inputs@Wx0+b0
__device__ __align__(16) float g_H1[(size_t)MB * HID];    // h1 for all t (fp32)
__device__ __align__(16) bf16  g_h0hi[2][BATCH][HID];
__device__ __align__(16) bf16  g_h0lo[2][BATCH][HID];
__device__ __align__(16) bf16  g_h1hi[2][BATCH][HID];
__device__ __align__(16) bf16  g_h1lo[2][BATCH][HID];
// packed split weights per CTA: [cta][comp(hi,lo)][32 n][1024 k] bf16
__device__ __align__(16) bf16  g_pWh0[(size_t)NCTA * 2 * 32 * HID];
__device__ __align__(16) bf16  g_pWx1[(size_t)NCTA * 2 * 32 * HID];
__device__ __align__(16) bf16  g_pWh1[(size_t)NCTA * 2 * 32 * HID];
__device__ unsigned g_bar_count = 0;
__device__ unsigned g_bar_gen   = 0;

// ---------------- grid barrier ---------------------------------------------
__device__ __forceinline__ void grid_barrier() {
    __syncthreads();
    __threadfence();
    if (threadIdx.x == 0) {
        unsigned gen = *(volatile unsigned*)&g_bar_gen;
        if (atomicAdd(&g_bar_count, 1u) == NCTA - 1) {
            *(volatile unsigned*)&g_bar_count = 0;
            __threadfence();
            *(volatile unsigned*)&g_bar_gen = gen + 1;
        } else {
            while (*(volatile unsigned*)&g_bar_gen == gen) { __nanosleep(20); }
        }
    }
    __syncthreads();
    __threadfence();
}

__device__ __forceinline__ float sigm(float x) { return 1.0f / (1.0f + expf(-x)); }

// ---------------- async copy helpers ---------------------------------------
__device__ __forceinline__ void cp16(void* dst, const void* src) {
    uint32_t d = (uint32_t)__cvta_generic_to_shared(dst);
    asm volatile("cp.async.cg.shared.global [%0], [%1], 16;" :: "r"(d), "l"(src));
}
__device__ __forceinline__ void cpcommit() { asm volatile("cp.async.commit_group;"); }
__device__ __forceinline__ void cpwait1()  { asm volatile("cp.async.wait_group 1;"); }
__device__ __forceinline__ void cpwait0()  { asm volatile("cp.async.wait_group 0;"); }

// ---------------- mma ------------------------------------------------------
__device__ __forceinline__ void mma_bf16(float* c, const uint32_t* a, const uint32_t* b) {
    asm volatile(
        "mma.sync.aligned.m16n8k16.row.col.f32.bf16.bf16.f32 "
        "{%0,%1,%2,%3}, {%4,%5,%6,%7}, {%8,%9}, {%0,%1,%2,%3};\n"
        : "+f"(c[0]), "+f"(c[1]), "+f"(c[2]), "+f"(c[3])
        : "r"(a[0]), "r"(a[1]), "r"(a[2]), "r"(a[3]), "r"(b[0]), "r"(b[1]));
}

// ---------------- dynamic smem layout --------------------------------------
struct SmemT {
    alignas(16) bf16  hHi[2][BATCH][KROW];   // staged h, hi
    alignas(16) bf16  hLo[2][BATCH][KROW];   // staged h, lo
    alignas(16) bf16  wHi[2][32][KROW];      // staged W, hi
    alignas(16) bf16  wLo[2][32][KROW];      // staged W, lo
    alignas(16) float sG[BATCH][33];         // gate preacts [m][n], padded
    alignas(16) float sc0[8][BATCH];         // c-state L0 (own cols)
    alignas(16) float sc1[8][BATCH];         // c-state L1
};

__device__ __forceinline__ void copy_chunk(SmemT* s, int buf, int k0,
        const bf16* __restrict__ hHiS, const bf16* __restrict__ hLoS,
        const bf16* __restrict__ wHiS, const bf16* __restrict__ wLoS, int tid) {
#pragma unroll
    for (int i = 0; i < 2; i++) {
        const int idx = tid + i * 256;
        const int row = idx >> 3;
        const int seg = (idx & 7) * 8;
        cp16(&s->hHi[buf][row][seg], hHiS + (size_t)row * HID + k0 + seg);
        cp16(&s->hLo[buf][row][seg], hLoS + (size_t)row * HID + k0 + seg);
    }
    const int row = tid >> 3;            // 0..31
    const int seg = (tid & 7) * 8;
    cp16(&s->wHi[buf][row][seg], wHiS + (size_t)row * HID + k0 + seg);
    cp16(&s->wLo[buf][row][seg], wLoS + (size_t)row * HID + k0 + seg);
}

__device__ __forceinline__ void mma_chunk(SmemT* s, int buf, float* c0, float* c1,
        int m0, int n0, int gid, int tid4) {
    const uint32_t* hH0 = (const uint32_t*)s->hHi[buf][m0 + gid];
    const uint32_t* hH8 = (const uint32_t*)s->hHi[buf][m0 + gid + 8];
    const uint32_t* hL0 = (const uint32_t*)s->hLo[buf][m0 + gid];
    const uint32_t* hL8 = (const uint32_t*)s->hLo[buf][m0 + gid + 8];
    const uint32_t* wHA = (const uint32_t*)s->wHi[buf][n0 + gid];
    const uint32_t* wHB = (const uint32_t*)s->wHi[buf][n0 + 8 + gid];
    const uint32_t* wLA = (const uint32_t*)s->wLo[buf][n0 + gid];
    const uint32_t* wLB = (const uint32_t*)s->wLo[buf][n0 + 8 + gid];
#pragma unroll
    for (int kk = 0; kk < KC / 16; kk++) {
        const int w = kk * 8 + tid4;
        uint32_t ah[4] = { hH0[w], hH8[w], hH0[w + 4], hH8[w + 4] };
        uint32_t al[4] = { hL0[w], hL8[w], hL0[w + 4], hL8[w + 4] };
        uint32_t bh0[2] = { wHA[w], wHA[w + 4] };
        uint32_t bh1[2] = { wHB[w], wHB[w + 4] };
        uint32_t bl0[2] = { wLA[w], wLA[w + 4] };
        uint32_t bl1[2] = { wLB[w], wLB[w + 4] };
        mma_bf16(c0, ah, bh0); mma_bf16(c0, ah, bl0); mma_bf16(c0, al, bh0);
        mma_bf16(c1, ah, bh1); mma_bf16(c1, ah, bl1); mma_bf16(c1, al, bh1);
    }
}

// one K=1024 pass: C += h(split) @ W(split), double-buffered
__device__ __forceinline__ void kpass(SmemT* s, float* c0, float* c1,
        const bf16* hHiS, const bf16* hLoS, const bf16* wHiS, const bf16* wLoS,
        int tid, int m0, int n0, int gid, int tid4) {
    copy_chunk(s, 0, 0, hHiS, hLoS, wHiS, wLoS, tid);
    cpcommit();
    const int NCH = HID / KC;   // 16
#pragma unroll 1
    for (int ch = 0; ch < NCH; ch++) {
        if (ch + 1 < NCH) {
            copy_chunk(s, (ch + 1) & 1, (ch + 1) * KC, hHiS, hLoS, wHiS, wLoS, tid);
            cpcommit();
            cpwait1();
        } else {
            cpwait0();
        }
        __syncthreads();
        mma_chunk(s, ch & 1, c0, c1, m0, n0, gid, tid4);
        __syncthreads();
    }
}

// ---------------- persistent recurrence kernel ------------------------------
extern __shared__ char smem_raw[];
__global__ void __launch_bounds__(256, 1) lstm_mma(
        const float* __restrict__ b1, float* __restrict__ out) {
    SmemT* s = (SmemT*)smem_raw;
    const int tid  = threadIdx.x;
    const int lane = tid & 31;
    const int wid  = tid >> 5;
    const int gid  = lane >> 2;      // 0..7
    const int tid4 = lane & 3;       // 0..3
    const int m0   = (wid & 3) * 16; // warp M-block
    const int n0   = (wid >> 2) * 16;// warp N-block (0 or 16)
    const int cta  = blockIdx.x;
    const int hc0  = cta * 8;

    const bf16* pW0h = g_pWh0 + (size_t)cta * 2 * 32 * HID;
    const bf16* pW0l = pW0h + (size_t)32 * HID;
    const bf16* pX1h = g_pWx1 + (size_t)cta * 2 * 32 * HID;
    const bf16* pX1l = pX1h + (size_t)32 * HID;
    const bf16* pH1h = g_pWh1 + (size_t)cta * 2 * 32 * HID;
    const bf16* pH1l = pH1h + (size_t)32 * HID;

    // ---- init state ----
    for (int e = tid; e < 512; e += 256) {
        const int m = e & 63, hc = e >> 6;
        s->sc0[hc][m] = 0.f;
        s->sc1[hc][m] = 0.f;
        g_h0hi[0][m][hc0 + hc] = __float2bfloat16(0.f);
        g_h0lo[0][m][hc0 + hc] = __float2bfloat16(0.f);
        g_h1hi[0][m][hc0 + hc] = __float2bfloat16(0.f);
        g_h1lo[0][m][hc0 + hc] = __float2bfloat16(0.f);
    }
    grid_barrier();

    for (int t = 0; t < T_STEPS; t++) {
        const int rbuf = t & 1;
        const int wbuf = rbuf ^ 1;

        // ======== phase A: G0 = GX[t] + h0 @ Wh0 ========
        float gxv[8];
        {
            const float* gx = g_GX + (size_t)(t * BATCH) * G4;
#pragma unroll
            for (int ns = 0; ns < 2; ns++)
#pragma unroll
                for (int j = 0; j < 4; j++) {
                    const int row = m0 + gid + ((j >> 1) << 3);
                    const int g   = (n0 >> 3) + ns;
                    const int jj  = 2 * tid4 + (j & 1);
                    gxv[ns * 4 + j] = gx[(size_t)row * G4 + g * HID + hc0 + jj];
                }
        }
        float c0[4] = {0.f, 0.f, 0.f, 0.f};
        float c1[4] = {0.f, 0.f, 0.f, 0.f};
        kpass(s, c0, c1, &g_h0hi[rbuf][0][0], &g_h0lo[rbuf][0][0],
              pW0h, pW0l, tid, m0, n0, gid, tid4);
#pragma unroll
        for (int j = 0; j < 4; j++) {
            const int row  = m0 + gid + ((j >> 1) << 3);
            const int col0 = n0 + 2 * tid4 + (j & 1);
            s->sG[row][col0]     = c0[j] + gxv[j];
            s->sG[row][col0 + 8] = c1[j] + gxv[4 + j];
        }
        __syncthreads();

        // act0 -> h0(hi,lo)[wbuf]
        for (int e = tid; e < 512; e += 256) {
            const int m = e & 63, hc = e >> 6;
            const float i_ = sigm(s->sG[m][hc]);
            const float f_ = sigm(s->sG[m][8 + hc]);
            const float cg = tanhf(s->sG[m][16 + hc]);
            const float o_ = sigm(s->sG[m][24 + hc]);
            const float cn = f_ * s->sc0[hc][m] + i_ * cg;
            s->sc0[hc][m] = cn;
            const float h = o_ * tanhf(cn);
            const bf16 hi = __float2bfloat16(h);
            const bf16 lo = __float2bfloat16(h - __bfloat162float(hi));
            g_h0hi[wbuf][m][hc0 + hc] = hi;
            g_h0lo[wbuf][m][hc0 + hc] = lo;
        }
        grid_barrier();

        // ======== phase B: G1 = b1 + h0new @ Wx1 + h1old @ Wh1 ========
        float bv[4];
#pragma unroll
        for (int ns = 0; ns < 2; ns++)
#pragma unroll
            for (int d = 0; d < 2; d++)
                bv[ns * 2 + d] = b1[((n0 >> 3) + ns) * HID + hc0 + 2 * tid4 + d];
#pragma unroll
        for (int j = 0; j < 4; j++) { c0[j] = 0.f; c1[j] = 0.f; }
        kpass(s, c0, c1, &g_h0hi[wbuf][0][0], &g_h0lo[wbuf][0][0],
              pX1h, pX1l, tid, m0, n0, gid, tid4);
        kpass(s, c0, c1, &g_h1hi[rbuf][0][0], &g_h1lo[rbuf][0][0],
              pH1h, pH1l, tid, m0, n0, gid, tid4);
#pragma unroll
        for (int j = 0; j < 4; j++) {
            const int row  = m0 + gid + ((j >> 1) << 3);
            const int col0 = n0 + 2 * tid4 + (j & 1);
            s->sG[row][col0]     = c0[j] + bv[j & 1];
            s->sG[row][col0 + 8] = c1[j] + bv[2 + (j & 1)];
        }
        __syncthreads();

        // act1 -> h1(hi,lo)[wbuf], g_H1[t]
        for (int e = tid; e < 512; e += 256) {
            const int m = e & 63, hc = e >> 6;
            const float i_ = sigm(s->sG[m][hc]);
            const float f_ = sigm(s->sG[m][8 + hc]);
            const float cg = tanhf(s->sG[m][16 + hc]);
            const float o_ = sigm(s->sG[m][24 + hc]);
            const float cn = f_ * s->sc1[hc][m] + i_ * cg;
            s->sc1[hc][m] = cn;
            const float h = o_ * tanhf(cn);
            const bf16 hi = __float2bfloat16(h);
            const bf16 lo = __float2bfloat16(h - __bfloat162float(hi));
            g_h1hi[wbuf][m][hc0 + hc] = hi;
            g_h1lo[wbuf][m][hc0 + hc] = lo;
            g_H1[((size_t)t * BATCH + m) * HID + hc0 + hc] = h;
        }
        grid_barrier();
    }

    // ---- tail: final_h, final_c (layer 1) ----
    for (int e = tid; e < 512; e += 256) {
        const int m = e & 63, hc = e >> 6;
        const size_t off = (size_t)MB * DOUT;
        out[off + (size_t)m * HID + hc0 + hc] =
            g_H1[((size_t)(T_STEPS - 1) * BATCH + m) * HID + hc0 + hc];
        out[off + (size_t)BATCH * HID + (size_t)m * HID + hc0 + hc] = s->sc1[hc][m];
    }
}

// ---------------- split/pack weights: W[k][4096] -> per-CTA bf16 hi/lo ------
__global__ __launch_bounds__(256) void pack_w_bf16(const float* __restrict__ W,
                                                   bf16* __restrict__ P) {
    const size_t total = (size_t)NCTA * 32 * HID;
    for (size_t idx = (size_t)blockIdx.x * blockDim.x + threadIdx.x;
         idx < total; idx += (size_t)gridDim.x * blockDim.x) {
        const int cta = (int)(idx >> 15);
        const int n   = (int)((idx >> 10) & 31);
        const int k   = (int)(idx & 1023);
        const int gcol = (n >> 3) * HID + cta * 8 + (n & 7);
        const float w = W[(size_t)k * G4 + gcol];
        const bf16 hi = __float2bfloat16(w);
        const bf16 lo = __float2bfloat16(w - __bfloat162float(hi));
        const size_t base = (size_t)cta * 2 * 32 * HID;
        P[base + (size_t)n * HID + k] = hi;
        P[base + (size_t)32 * HID + (size_t)n * HID + k] = lo;
    }
}

// ---------------- big GEMM: C[M,N] = A[M,K] @ B[K,N] + bias[N] -------------
__global__ __launch_bounds__(256) void gemm_bias_kernel(
        const float* __restrict__ A,
        const float* __restrict__ B,
        const float* __restrict__ bias,
        float* __restrict__ C,
        int M, int N, int K) {
    __shared__ float As[8][72];
    __shared__ float Bs[8][64];
    const int tid = threadIdx.x;
    const int colBase = blockIdx.x * 64;
    const int rowBase = blockIdx.y * 64;
    const int tx = tid & 15, ty = tid >> 4;

    float acc[4][4] = {};

    const int ar  = tid >> 2;
    const int akp = (tid & 3) * 2;
    const int bk  = tid >> 5;
    const int bc  = (tid & 31) * 2;

    const float* Aptr = A + (size_t)(rowBase + ar) * K + akp;
    const float* Bptr = B + (size_t)bk * N + colBase + bc;

    for (int k0 = 0; k0 < K; k0 += 8) {
        float2 av = *(const float2*)(Aptr + k0);
        float2 bv = *(const float2*)(Bptr + (size_t)k0 * N);
        __syncthreads();
        As[akp][ar]     = av.x;
        As[akp + 1][ar] = av.y;
        *(float2*)&Bs[bk][bc] = bv;
        __syncthreads();
#pragma unroll
        for (int kk = 0; kk < 8; kk++) {
            float a[4], b[4];
            *(float4*)a = *(const float4*)&As[kk][ty * 4];
            *(float4*)b = *(const float4*)&Bs[kk][tx * 4];
#pragma unroll
            for (int i = 0; i < 4; i++)
#pragma unroll
                for (int j = 0; j < 4; j++)
                    acc[i][j] += a[i] * b[j];
        }
    }
#pragma unroll
    for (int i = 0; i < 4; i++) {
        const int r = rowBase + ty * 4 + i;
#pragma unroll
        for (int j = 0; j < 4; j++) {
            const int c = colBase + tx * 4 + j;
            C[(size_t)r * N + c] = acc[i][j] + bias[c];
        }
    }
}

// ---------------- launch ----------------------------------------------------
extern "C" void kernel_launch(void* const* d_in, const int* in_sizes, int n_in,
                              void* d_out, int out_size) {
    const float* inputs = (const float*)d_in[0];
    const float* Wx0    = (const float*)d_in[1];
    const float* Wh0    = (const float*)d_in[2];
    const float* b0     = (const float*)d_in[3];
    const float* Wx1    = (const float*)d_in[4];
    const float* Wh1    = (const float*)d_in[5];
    const float* b1     = (const float*)d_in[6];
    const float* Wout   = (const float*)d_in[7];
    const float* bout   = (const float*)d_in[8];
    float* out = (float*)d_out;

    float *pGX, *pH1;
    bf16 *pp0, *pp1, *pp2;
    cudaGetSymbolAddress((void**)&pGX, g_GX);
    cudaGetSymbolAddress((void**)&pH1, g_H1);
    cudaGetSymbolAddress((void**)&pp0, g_pWh0);
    cudaGetSymbolAddress((void**)&pp1, g_pWx1);
    cudaGetSymbolAddress((void**)&pp2, g_pWh1);

    // allow large dynamic smem for the persistent kernel
    cudaFuncSetAttribute(lstm_mma, cudaFuncAttributeMaxDynamicSharedMemorySize,
                         (int)sizeof(SmemT));

    // 0) split+pack recurrent weights (bf16 hi/lo, per-CTA tiles)
    pack_w_bf16<<<1024, 256>>>(Wh0, pp0);
    pack_w_bf16<<<1024, 256>>>(Wx1, pp1);
    pack_w_bf16<<<1024, 256>>>(Wh1, pp2);

    // 1) precompute GX = inputs @ Wx0 + b0   [16384 x 4096]
    gemm_bias_kernel<<<dim3(G4 / 64, MB / 64), 256>>>(inputs, Wx0, b0, pGX,
                                                      MB, G4, DIN);

    // 2) full 256-step recurrence, tensor-core persistent kernel
    lstm_mma<<<NCTA, 256, sizeof(SmemT)>>>(b1, out);

    // 3) outs = H1_all @ Wout + bout
    gemm_bias_kernel<<<dim3(DOUT / 64, MB / 64), 256>>>(pH1, Wout, bout, out,
                                                        MB, DOUT, HID);
}

// round 9
// speedup vs baseline: 8.5566x; 1.1564x over previous
#include <cuda_runtime.h>
#include <cuda_bf16.h>
#include <math.h>
#include <stdint.h>
#include <stddef.h>

#define T_STEPS 256
#define BATCH   64
#define DIN     512
#define HID     1024
#define DOUT    512
#define G4      (4*HID)          /* 4096 */
#define MB      (T_STEPS*BATCH)  /* 16384 */
#define NCTA    128
#define KC      128              /* recurrence k-chunk */
#define KROW    136              /* padded bf16 elems per smem row */

typedef __nv_bfloat16 bf16;

// ---------------- scratch (device globals; no runtime allocation) ----------
__device__ __align__(16) float g_GX[(size_t)MB * G4];      // inputs@Wx0+b0
__device__ __align__(16) bf16  g_inHi[(size_t)MB * DIN];   // split inputs
__device__ __align__(16) bf16  g_inLo[(size_t)MB * DIN];
__device__ __align__(16) bf16  g_Wx0Thi[(size_t)G4 * DIN]; // Wx0 transposed [N][K]
__device__ __align__(16) bf16  g_Wx0Tlo[(size_t)G4 * DIN];
__device__ __align__(16) bf16  g_WoutThi[(size_t)DOUT * HID];
__device__ __align__(16) bf16  g_WoutTlo[(size_t)DOUT * HID];
__device__ __align__(16) bf16  g_H1hi[(size_t)MB * HID];   // h1 planes for all t
__device__ __align__(16) bf16  g_H1lo[(size_t)MB * HID];
__device__ __align__(16) bf16  g_h0hi[2][BATCH][HID];
__device__ __align__(16) bf16  g_h0lo[2][BATCH][HID];
__device__ __align__(16) bf16  g_h1hi[2][BATCH][HID];
__device__ __align__(16) bf16  g_h1lo[2][BATCH][HID];
__device__ __align__(16) bf16  g_pWh0[(size_t)NCTA * 2 * 32 * HID];
__device__ __align__(16) bf16  g_pWx1[(size_t)NCTA * 2 * 32 * HID];
__device__ __align__(16) bf16  g_pWh1[(size_t)NCTA * 2 * 32 * HID];
__device__ unsigned g_bar_count = 0;
__device__ unsigned g_bar_gen   = 0;

// ---------------- grid barrier ---------------------------------------------
__device__ __forceinline__ void grid_barrier() {
    __syncthreads();
    __threadfence();
    if (threadIdx.x == 0) {
        unsigned gen = *(volatile unsigned*)&g_bar_gen;
        if (atomicAdd(&g_bar_count, 1u) == NCTA - 1) {
            *(volatile unsigned*)&g_bar_count = 0;
            __threadfence();
            *(volatile unsigned*)&g_bar_gen = gen + 1;
        } else {
            while (*(volatile unsigned*)&g_bar_gen == gen) { __nanosleep(20); }
        }
    }
    __syncthreads();
    __threadfence();
}

__device__ __forceinline__ float sigm(float x) { return 1.0f / (1.0f + expf(-x)); }

// ---------------- async copy helpers ---------------------------------------
__device__ __forceinline__ void cp16(void* dst, const void* src) {
    uint32_t d = (uint32_t)__cvta_generic_to_shared(dst);
    asm volatile("cp.async.cg.shared.global [%0], [%1], 16;" :: "r"(d), "l"(src));
}
__device__ __forceinline__ void cpcommit() { asm volatile("cp.async.commit_group;"); }
__device__ __forceinline__ void cpwait1()  { asm volatile("cp.async.wait_group 1;"); }
__device__ __forceinline__ void cpwait0()  { asm volatile("cp.async.wait_group 0;"); }

// ---------------- mma ------------------------------------------------------
__device__ __forceinline__ void mma_bf16(float* c, const uint32_t* a, const uint32_t* b) {
    asm volatile(
        "mma.sync.aligned.m16n8k16.row.col.f32.bf16.bf16.f32 "
        "{%0,%1,%2,%3}, {%4,%5,%6,%7}, {%8,%9}, {%0,%1,%2,%3};\n"
        : "+f"(c[0]), "+f"(c[1]), "+f"(c[2]), "+f"(c[3])
        : "r"(a[0]), "r"(a[1]), "r"(a[2]), "r"(a[3]), "r"(b[0]), "r"(b[1]));
}

extern __shared__ char smem_raw[];

// ======================= persistent recurrence ==============================
struct SmemT {
    alignas(16) bf16  hHi[2][BATCH][KROW];
    alignas(16) bf16  hLo[2][BATCH][KROW];
    alignas(16) bf16  wHi[2][32][KROW];
    alignas(16) bf16  wLo[2][32][KROW];
    alignas(16) float sG[BATCH][33];
    alignas(16) float sc0[8][BATCH];
    alignas(16) float sc1[8][BATCH];
};

__device__ __forceinline__ void copy_chunk(SmemT* s, int buf, int k0,
        const bf16* __restrict__ hHiS, const bf16* __restrict__ hLoS,
        const bf16* __restrict__ wHiS, const bf16* __restrict__ wLoS, int tid) {
#pragma unroll
    for (int i = 0; i < 4; i++) {                 // h: 64 rows x 128 el per plane
        const int idx = tid + i * 256;
        const int row = idx >> 4;
        const int seg = (idx & 15) * 8;
        cp16(&s->hHi[buf][row][seg], hHiS + (size_t)row * HID + k0 + seg);
        cp16(&s->hLo[buf][row][seg], hLoS + (size_t)row * HID + k0 + seg);
    }
#pragma unroll
    for (int i = 0; i < 2; i++) {                 // w: 32 rows x 128 el per plane
        const int idx = tid + i * 256;
        const int row = idx >> 4;
        const int seg = (idx & 15) * 8;
        cp16(&s->wHi[buf][row][seg], wHiS + (size_t)row * HID + k0 + seg);
        cp16(&s->wLo[buf][row][seg], wLoS + (size_t)row * HID + k0 + seg);
    }
}

__device__ __forceinline__ void mma_chunk(SmemT* s, int buf, float* c0, float* c1,
        int m0, int n0, int gid, int tid4) {
    const uint32_t* hH0 = (const uint32_t*)s->hHi[buf][m0 + gid];
    const uint32_t* hH8 = (const uint32_t*)s->hHi[buf][m0 + gid + 8];
    const uint32_t* hL0 = (const uint32_t*)s->hLo[buf][m0 + gid];
    const uint32_t* hL8 = (const uint32_t*)s->hLo[buf][m0 + gid + 8];
    const uint32_t* wHA = (const uint32_t*)s->wHi[buf][n0 + gid];
    const uint32_t* wHB = (const uint32_t*)s->wHi[buf][n0 + 8 + gid];
    const uint32_t* wLA = (const uint32_t*)s->wLo[buf][n0 + gid];
    const uint32_t* wLB = (const uint32_t*)s->wLo[buf][n0 + 8 + gid];
#pragma unroll
    for (int kk = 0; kk < KC / 16; kk++) {
        const int w = kk * 8 + tid4;
        uint32_t ah[4] = { hH0[w], hH8[w], hH0[w + 4], hH8[w + 4] };
        uint32_t al[4] = { hL0[w], hL8[w], hL0[w + 4], hL8[w + 4] };
        uint32_t bh0[2] = { wHA[w], wHA[w + 4] };
        uint32_t bh1[2] = { wHB[w], wHB[w + 4] };
        uint32_t bl0[2] = { wLA[w], wLA[w + 4] };
        uint32_t bl1[2] = { wLB[w], wLB[w + 4] };
        mma_bf16(c0, ah, bh0); mma_bf16(c0, ah, bl0); mma_bf16(c0, al, bh0);
        mma_bf16(c1, ah, bh1); mma_bf16(c1, ah, bl1); mma_bf16(c1, al, bh1);
    }
}

__device__ __forceinline__ void kpass(SmemT* s, float* c0, float* c1,
        const bf16* hHiS, const bf16* hLoS, const bf16* wHiS, const bf16* wLoS,
        int tid, int m0, int n0, int gid, int tid4) {
    copy_chunk(s, 0, 0, hHiS, hLoS, wHiS, wLoS, tid);
    cpcommit();
    const int NCH = HID / KC;   // 8
#pragma unroll 1
    for (int ch = 0; ch < NCH; ch++) {
        if (ch + 1 < NCH) {
            copy_chunk(s, (ch + 1) & 1, (ch + 1) * KC, hHiS, hLoS, wHiS, wLoS, tid);
            cpcommit();
            cpwait1();
        } else {
            cpwait0();
        }
        __syncthreads();
        mma_chunk(s, ch & 1, c0, c1, m0, n0, gid, tid4);
        __syncthreads();
    }
}

__global__ void __launch_bounds__(256, 1) lstm_mma(
        const float* __restrict__ b1, float* __restrict__ out) {
    SmemT* s = (SmemT*)smem_raw;
    const int tid  = threadIdx.x;
    const int lane = tid & 31;
    const int wid  = tid >> 5;
    const int gid  = lane >> 2;
    const int tid4 = lane & 3;
    const int m0   = (wid & 3) * 16;
    const int n0   = (wid >> 2) * 16;
    const int cta  = blockIdx.x;
    const int hc0  = cta * 8;

    const bf16* pW0h = g_pWh0 + (size_t)cta * 2 * 32 * HID;
    const bf16* pW0l = pW0h + (size_t)32 * HID;
    const bf16* pX1h = g_pWx1 + (size_t)cta * 2 * 32 * HID;
    const bf16* pX1l = pX1h + (size_t)32 * HID;
    const bf16* pH1h = g_pWh1 + (size_t)cta * 2 * 32 * HID;
    const bf16* pH1l = pH1h + (size_t)32 * HID;

    for (int e = tid; e < 512; e += 256) {
        const int m = e & 63, hc = e >> 6;
        s->sc0[hc][m] = 0.f;
        s->sc1[hc][m] = 0.f;
        g_h0hi[0][m][hc0 + hc] = __float2bfloat16(0.f);
        g_h0lo[0][m][hc0 + hc] = __float2bfloat16(0.f);
        g_h1hi[0][m][hc0 + hc] = __float2bfloat16(0.f);
        g_h1lo[0][m][hc0 + hc] = __float2bfloat16(0.f);
    }
    grid_barrier();

    for (int t = 0; t < T_STEPS; t++) {
        const int rbuf = t & 1;
        const int wbuf = rbuf ^ 1;

        // ---- phase A: G0 = GX[t] + h0 @ Wh0 ----
        float gxv[8];
        {
            const float* gx = g_GX + (size_t)(t * BATCH) * G4;
#pragma unroll
            for (int ns = 0; ns < 2; ns++)
#pragma unroll
                for (int j = 0; j < 4; j++) {
                    const int row = m0 + gid + ((j >> 1) << 3);
                    const int g   = (n0 >> 3) + ns;
                    const int jj  = 2 * tid4 + (j & 1);
                    gxv[ns * 4 + j] = gx[(size_t)row * G4 + g * HID + hc0 + jj];
                }
        }
        float c0[4] = {0.f, 0.f, 0.f, 0.f};
        float c1[4] = {0.f, 0.f, 0.f, 0.f};
        kpass(s, c0, c1, &g_h0hi[rbuf][0][0], &g_h0lo[rbuf][0][0],
              pW0h, pW0l, tid, m0, n0, gid, tid4);
#pragma unroll
        for (int j = 0; j < 4; j++) {
            const int row  = m0 + gid + ((j >> 1) << 3);
            const int col0 = n0 + 2 * tid4 + (j & 1);
            s->sG[row][col0]     = c0[j] + gxv[j];
            s->sG[row][col0 + 8] = c1[j] + gxv[4 + j];
        }
        __syncthreads();

        for (int e = tid; e < 512; e += 256) {
            const int m = e & 63, hc = e >> 6;
            const float i_ = sigm(s->sG[m][hc]);
            const float f_ = sigm(s->sG[m][8 + hc]);
            const float cg = tanhf(s->sG[m][16 + hc]);
            const float o_ = sigm(s->sG[m][24 + hc]);
            const float cn = f_ * s->sc0[hc][m] + i_ * cg;
            s->sc0[hc][m] = cn;
            const float h = o_ * tanhf(cn);
            const bf16 hi = __float2bfloat16(h);
            const bf16 lo = __float2bfloat16(h - __bfloat162float(hi));
            g_h0hi[wbuf][m][hc0 + hc] = hi;
            g_h0lo[wbuf][m][hc0 + hc] = lo;
        }
        grid_barrier();

        // ---- phase B: G1 = b1 + h0new @ Wx1 + h1old @ Wh1 ----
        float bv[4];
#pragma unroll
        for (int ns = 0; ns < 2; ns++)
#pragma unroll
            for (int d = 0; d < 2; d++)
                bv[ns * 2 + d] = b1[((n0 >> 3) + ns) * HID + hc0 + 2 * tid4 + d];
#pragma unroll
        for (int j = 0; j < 4; j++) { c0[j] = 0.f; c1[j] = 0.f; }
        kpass(s, c0, c1, &g_h0hi[wbuf][0][0], &g_h0lo[wbuf][0][0],
              pX1h, pX1l, tid, m0, n0, gid, tid4);
        kpass(s, c0, c1, &g_h1hi[rbuf][0][0], &g_h1lo[rbuf][0][0],
              pH1h, pH1l, tid, m0, n0, gid, tid4);
#pragma unroll
        for (int j = 0; j < 4; j++) {
            const int row  = m0 + gid + ((j >> 1) << 3);
            const int col0 = n0 + 2 * tid4 + (j & 1);
            s->sG[row][col0]     = c0[j] + bv[j & 1];
            s->sG[row][col0 + 8] = c1[j] + bv[2 + (j & 1)];
        }
        __syncthreads();

        for (int e = tid; e < 512; e += 256) {
            const int m = e & 63, hc = e >> 6;
            const float i_ = sigm(s->sG[m][hc]);
            const float f_ = sigm(s->sG[m][8 + hc]);
            const float cg = tanhf(s->sG[m][16 + hc]);
            const float o_ = sigm(s->sG[m][24 + hc]);
            const float cn = f_ * s->sc1[hc][m] + i_ * cg;
            s->sc1[hc][m] = cn;
            const float h = o_ * tanhf(cn);
            const bf16 hi = __float2bfloat16(h);
            const bf16 lo = __float2bfloat16(h - __bfloat162float(hi));
            g_h1hi[wbuf][m][hc0 + hc] = hi;
            g_h1lo[wbuf][m][hc0 + hc] = lo;
            g_H1hi[((size_t)t * BATCH + m) * HID + hc0 + hc] = hi;
            g_H1lo[((size_t)t * BATCH + m) * HID + hc0 + hc] = lo;
        }
        grid_barrier();
    }

    // ---- tail: final_h, final_c (layer 1) ----
    const int fbuf = ((T_STEPS - 1) & 1) ^ 1;
    for (int e = tid; e < 512; e += 256) {
        const int m = e & 63, hc = e >> 6;
        const size_t off = (size_t)MB * DOUT;
        const float h = __bfloat162float(g_h1hi[fbuf][m][hc0 + hc]) +
                        __bfloat162float(g_h1lo[fbuf][m][hc0 + hc]);
        out[off + (size_t)m * HID + hc0 + hc] = h;
        out[off + (size_t)BATCH * HID + (size_t)m * HID + hc0 + hc] = s->sc1[hc][m];
    }
}

// ======================= big tensor-core GEMM ===============================
// C[M,N] = Ahi/lo[M,K] @ (BT hi/lo)[N,K]^T + bias, split-bf16 (3 mma).
#define GBK 32
struct GSmem {
    alignas(16) bf16 aHi[2][128][GBK + 8];
    alignas(16) bf16 aLo[2][128][GBK + 8];
    alignas(16) bf16 bHi[2][128][GBK + 8];
    alignas(16) bf16 bLo[2][128][GBK + 8];
};

__device__ __forceinline__ void g_copy(GSmem* s, int buf, int k0,
        const bf16* __restrict__ AHi, const bf16* __restrict__ ALo,
        const bf16* __restrict__ BHi, const bf16* __restrict__ BLo,
        int K, int rowA, int rowB, int tid) {
#pragma unroll
    for (int i = 0; i < 2; i++) {
        const int idx = tid + i * 256;
        const int row = idx >> 2;
        const int seg = (idx & 3) * 8;
        cp16(&s->aHi[buf][row][seg], AHi + (size_t)(rowA + row) * K + k0 + seg);
        cp16(&s->aLo[buf][row][seg], ALo + (size_t)(rowA + row) * K + k0 + seg);
        cp16(&s->bHi[buf][row][seg], BHi + (size_t)(rowB + row) * K + k0 + seg);
        cp16(&s->bLo[buf][row][seg], BLo + (size_t)(rowB + row) * K + k0 + seg);
    }
}

__global__ void __launch_bounds__(256, 1) gemm_mma_big(
        const bf16* __restrict__ AHi, const bf16* __restrict__ ALo,
        const bf16* __restrict__ BHi, const bf16* __restrict__ BLo,
        const float* __restrict__ bias, float* __restrict__ C,
        int M, int N, int K) {
    GSmem* s = (GSmem*)smem_raw;
    const int tid  = threadIdx.x;
    const int lane = tid & 31;
    const int wid  = tid >> 5;
    const int gid  = lane >> 2;
    const int tid4 = lane & 3;
    const int m0w  = (wid & 1) * 64;
    const int n0w  = (wid >> 1) * 32;
    const int rowA = blockIdx.y * 128;
    const int rowB = blockIdx.x * 128;

    float acc[4][4][4];
#pragma unroll
    for (int a = 0; a < 4; a++)
#pragma unroll
        for (int b = 0; b < 4; b++)
#pragma unroll
            for (int c = 0; c < 4; c++) acc[a][b][c] = 0.f;

    g_copy(s, 0, 0, AHi, ALo, BHi, BLo, K, rowA, rowB, tid);
    cpcommit();
    const int NCH = K / GBK;
#pragma unroll 1
    for (int ch = 0; ch < NCH; ch++) {
        if (ch + 1 < NCH) {
            g_copy(s, (ch + 1) & 1, (ch + 1) * GBK, AHi, ALo, BHi, BLo, K, rowA, rowB, tid);
            cpcommit();
            cpwait1();
        } else {
            cpwait0();
        }
        __syncthreads();
        const int buf = ch & 1;
#pragma unroll
        for (int kk = 0; kk < GBK / 16; kk++) {
            const int w = kk * 8 + tid4;
#pragma unroll
            for (int mt = 0; mt < 4; mt++) {
                const uint32_t* aH0 = (const uint32_t*)s->aHi[buf][m0w + mt * 16 + gid];
                const uint32_t* aH8 = (const uint32_t*)s->aHi[buf][m0w + mt * 16 + gid + 8];
                const uint32_t* aL0 = (const uint32_t*)s->aLo[buf][m0w + mt * 16 + gid];
                const uint32_t* aL8 = (const uint32_t*)s->aLo[buf][m0w + mt * 16 + gid + 8];
                uint32_t ah[4] = { aH0[w], aH8[w], aH0[w + 4], aH8[w + 4] };
                uint32_t al[4] = { aL0[w], aL8[w], aL0[w + 4], aL8[w + 4] };
#pragma unroll
                for (int nt = 0; nt < 4; nt++) {
                    const uint32_t* bH = (const uint32_t*)s->bHi[buf][n0w + nt * 8 + gid];
                    const uint32_t* bL = (const uint32_t*)s->bLo[buf][n0w + nt * 8 + gid];
                    uint32_t bh[2] = { bH[w], bH[w + 4] };
                    uint32_t bl[2] = { bL[w], bL[w + 4] };
                    mma_bf16(acc[mt][nt], ah, bh);
                    mma_bf16(acc[mt][nt], ah, bl);
                    mma_bf16(acc[mt][nt], al, bh);
                }
            }
        }
        __syncthreads();
    }

#pragma unroll
    for (int mt = 0; mt < 4; mt++)
#pragma unroll
        for (int nt = 0; nt < 4; nt++)
#pragma unroll
            for (int j = 0; j < 4; j++) {
                const int r = rowA + m0w + mt * 16 + gid + ((j >> 1) << 3);
                const int c = rowB + n0w + nt * 8 + 2 * tid4 + (j & 1);
                C[(size_t)r * N + c] = acc[mt][nt][j] + bias[c];
            }
}

// ======================= packing kernels ====================================
__global__ __launch_bounds__(256) void split_rows(const float* __restrict__ src,
        bf16* __restrict__ hi, bf16* __restrict__ lo, size_t n) {
    for (size_t i = (size_t)blockIdx.x * blockDim.x + threadIdx.x;
         i < n; i += (size_t)gridDim.x * blockDim.x) {
        const float v = src[i];
        const bf16 h = __float2bfloat16(v);
        hi[i] = h;
        lo[i] = __float2bfloat16(v - __bfloat162float(h));
    }
}

// dst[n][k] = src[k][n]  (split)
__global__ __launch_bounds__(256) void split_transpose(const float* __restrict__ src,
        bf16* __restrict__ hi, bf16* __restrict__ lo, int K, int N) {
    const size_t total = (size_t)K * N;
    for (size_t i = (size_t)blockIdx.x * blockDim.x + threadIdx.x;
         i < total; i += (size_t)gridDim.x * blockDim.x) {
        const int n = (int)(i / K);
        const int k = (int)(i % K);
        const float v = src[(size_t)k * N + n];
        const bf16 h = __float2bfloat16(v);
        hi[i] = h;
        lo[i] = __float2bfloat16(v - __bfloat162float(h));
    }
}

__global__ __launch_bounds__(256) void pack_w_bf16(const float* __restrict__ W,
                                                   bf16* __restrict__ P) {
    const size_t total = (size_t)NCTA * 32 * HID;
    for (size_t idx = (size_t)blockIdx.x * blockDim.x + threadIdx.x;
         idx < total; idx += (size_t)gridDim.x * blockDim.x) {
        const int cta = (int)(idx >> 15);
        const int n   = (int)((idx >> 10) & 31);
        const int k   = (int)(idx & 1023);
        const int gcol = (n >> 3) * HID + cta * 8 + (n & 7);
        const float w = W[(size_t)k * G4 + gcol];
        const bf16 hi = __float2bfloat16(w);
        const bf16 lo = __float2bfloat16(w - __bfloat162float(hi));
        const size_t base = (size_t)cta * 2 * 32 * HID;
        P[base + (size_t)n * HID + k] = hi;
        P[base + (size_t)32 * HID + (size_t)n * HID + k] = lo;
    }
}

// ---------------- launch ----------------------------------------------------
extern "C" void kernel_launch(void* const* d_in, const int* in_sizes, int n_in,
                              void* d_out, int out_size) {
    const float* inputs = (const float*)d_in[0];
    const float* Wx0    = (const float*)d_in[1];
    const float* Wh0    = (const float*)d_in[2];
    const float* b0     = (const float*)d_in[3];
    const float* Wx1    = (const float*)d_in[4];
    const float* Wh1    = (const float*)d_in[5];
    const float* b1     = (const float*)d_in[6];
    const float* Wout   = (const float*)d_in[7];
    const float* bout   = (const float*)d_in[8];
    float* out = (float*)d_out;

    float *pGX;
    bf16 *pp0, *pp1, *pp2, *pinH, *pinL, *pWx0h, *pWx0l, *pWoh, *pWol, *pH1h, *pH1l;
    cudaGetSymbolAddress((void**)&pGX,   g_GX);
    cudaGetSymbolAddress((void**)&pp0,   g_pWh0);
    cudaGetSymbolAddress((void**)&pp1,   g_pWx1);
    cudaGetSymbolAddress((void**)&pp2,   g_pWh1);
    cudaGetSymbolAddress((void**)&pinH,  g_inHi);
    cudaGetSymbolAddress((void**)&pinL,  g_inLo);
    cudaGetSymbolAddress((void**)&pWx0h, g_Wx0Thi);
    cudaGetSymbolAddress((void**)&pWx0l, g_Wx0Tlo);
    cudaGetSymbolAddress((void**)&pWoh,  g_WoutThi);
    cudaGetSymbolAddress((void**)&pWol,  g_WoutTlo);
    cudaGetSymbolAddress((void**)&pH1h,  g_H1hi);
    cudaGetSymbolAddress((void**)&pH1l,  g_H1lo);

    cudaFuncSetAttribute(lstm_mma, cudaFuncAttributeMaxDynamicSharedMemorySize,
                         (int)sizeof(SmemT));
    cudaFuncSetAttribute(gemm_mma_big, cudaFuncAttributeMaxDynamicSharedMemorySize,
                         (int)sizeof(GSmem));

    // 0) packing / splitting
    pack_w_bf16<<<1024, 256>>>(Wh0, pp0);
    pack_w_bf16<<<1024, 256>>>(Wx1, pp1);
    pack_w_bf16<<<1024, 256>>>(Wh1, pp2);
    split_rows<<<2048, 256>>>(inputs, pinH, pinL, (size_t)MB * DIN);
    split_transpose<<<1024, 256>>>(Wx0, pWx0h, pWx0l, DIN, G4);
    split_transpose<<<512, 256>>>(Wout, pWoh, pWol, HID, DOUT);

    // 1) GX = inputs @ Wx0 + b0   [16384 x 4096]  (tensor cores)
    gemm_mma_big<<<dim3(G4 / 128, MB / 128), 256, sizeof(GSmem)>>>(
        pinH, pinL, pWx0h, pWx0l, b0, pGX, MB, G4, DIN);

    // 2) full 256-step recurrence, tensor-core persistent kernel
    lstm_mma<<<NCTA, 256, sizeof(SmemT)>>>(b1, out);

    // 3) outs = H1_all @ Wout + bout  (tensor cores)
    gemm_mma_big<<<dim3(DOUT / 128, MB / 128), 256, sizeof(GSmem)>>>(
        pH1h, pH1l, pWoh, pWol, bout, out, MB, DOUT, HID);
}

// round 11
// speedup vs baseline: 10.5046x; 1.2277x over previous
#include <cuda_runtime.h>
#include <cuda_bf16.h>
#include <math.h>
#include <stdint.h>
#include <stddef.h>

#define T_STEPS 256
#define BATCH   64
#define DIN     512
#define HID     1024
#define DOUT    512
#define G4      (4*HID)          /* 4096 */
#define MB      (T_STEPS*BATCH)  /* 16384 */
#define NCTA    128
#define KC      64               /* fused-superstep k-chunk */
#define KR      72               /* padded bf16 row (anti-conflict) */

typedef __nv_bfloat16 bf16;

// ---------------- scratch (device globals; no runtime allocation) ----------
__device__ __align__(16) float g_GX[(size_t)MB * G4];      // inputs@Wx0+b0
__device__ __align__(16) bf16  g_inHi[(size_t)MB * DIN];
__device__ __align__(16) bf16  g_inLo[(size_t)MB * DIN];
__device__ __align__(16) bf16  g_Wx0Thi[(size_t)G4 * DIN];
__device__ __align__(16) bf16  g_Wx0Tlo[(size_t)G4 * DIN];
__device__ __align__(16) bf16  g_WoutThi[(size_t)DOUT * HID];
__device__ __align__(16) bf16  g_WoutTlo[(size_t)DOUT * HID];
__device__ __align__(16) bf16  g_H1hi[(size_t)MB * HID];
__device__ __align__(16) bf16  g_H1lo[(size_t)MB * HID];
__device__ __align__(16) bf16  g_h0hi[2][BATCH][HID];
__device__ __align__(16) bf16  g_h0lo[2][BATCH][HID];
__device__ __align__(16) bf16  g_h1hi[2][BATCH][HID];
__device__ __align__(16) bf16  g_h1lo[2][BATCH][HID];
__device__ __align__(16) bf16  g_pWh0[(size_t)NCTA * 2 * 32 * HID];
__device__ __align__(16) bf16  g_pWx1[(size_t)NCTA * 2 * 32 * HID];
__device__ __align__(16) bf16  g_pWh1[(size_t)NCTA * 2 * 32 * HID];
__device__ unsigned g_bar_count = 0;
__device__ unsigned g_bar_gen   = 0;

// ---------------- grid barrier ---------------------------------------------
__device__ __forceinline__ void grid_barrier() {
    __syncthreads();
    __threadfence();
    if (threadIdx.x == 0) {
        unsigned gen = *(volatile unsigned*)&g_bar_gen;
        if (atomicAdd(&g_bar_count, 1u) == NCTA - 1) {
            *(volatile unsigned*)&g_bar_count = 0;
            __threadfence();
            *(volatile unsigned*)&g_bar_gen = gen + 1;
        } else {
            while (*(volatile unsigned*)&g_bar_gen == gen) { __nanosleep(20); }
        }
    }
    __syncthreads();
    __threadfence();
}

__device__ __forceinline__ float sigm(float x) { return 1.0f / (1.0f + expf(-x)); }

// ---------------- async copy helpers ---------------------------------------
__device__ __forceinline__ void cp16(void* dst, const void* src) {
    uint32_t d = (uint32_t)__cvta_generic_to_shared(dst);
    asm volatile("cp.async.cg.shared.global [%0], [%1], 16;" :: "r"(d), "l"(src));
}
__device__ __forceinline__ void cpcommit() { asm volatile("cp.async.commit_group;"); }
__device__ __forceinline__ void cpwait1()  { asm volatile("cp.async.wait_group 1;"); }
__device__ __forceinline__ void cpwait0()  { asm volatile("cp.async.wait_group 0;"); }

// ---------------- mma ------------------------------------------------------
__device__ __forceinline__ void mma_bf16(float* c, const uint32_t* a, const uint32_t* b) {
    asm volatile(
        "mma.sync.aligned.m16n8k16.row.col.f32.bf16.bf16.f32 "
        "{%0,%1,%2,%3}, {%4,%5,%6,%7}, {%8,%9}, {%0,%1,%2,%3};\n"
        : "+f"(c[0]), "+f"(c[1]), "+f"(c[2]), "+f"(c[3])
        : "r"(a[0]), "r"(a[1]), "r"(a[2]), "r"(a[3]), "r"(b[0]), "r"(b[1]));
}

extern __shared__ char smem_raw[];

// ======================= fused persistent recurrence ========================
// Superstep t: G1(t) = b1 + h0(t)@Wx1 + h1(t-1)@Wh1  (sG cols 0..31)
//              G0(t+1) = GX[t+1] + h0(t)@Wh0         (sG cols 32..63)
// then act1 -> h1(t), act0 -> h0(t+1). ONE grid barrier per step.
struct SmemT {
    alignas(16) bf16  h0Hi[2][BATCH][KR];
    alignas(16) bf16  h0Lo[2][BATCH][KR];
    alignas(16) bf16  h1Hi[2][BATCH][KR];
    alignas(16) bf16  h1Lo[2][BATCH][KR];
    alignas(16) bf16  w0Hi[2][32][KR];   // Wh0
    alignas(16) bf16  w0Lo[2][32][KR];
    alignas(16) bf16  wxHi[2][32][KR];   // Wx1
    alignas(16) bf16  wxLo[2][32][KR];
    alignas(16) bf16  whHi[2][32][KR];   // Wh1
    alignas(16) bf16  whLo[2][32][KR];
    alignas(16) float sG[BATCH][68];
    alignas(16) float sc0[8][BATCH];
    alignas(16) float sc1[8][BATCH];
};

__device__ __forceinline__ void copy_chunk(SmemT* s, int buf, int k0,
        const bf16* __restrict__ h0h, const bf16* __restrict__ h0l,
        const bf16* __restrict__ h1h, const bf16* __restrict__ h1l,
        const bf16* __restrict__ w0h, const bf16* __restrict__ w0l,
        const bf16* __restrict__ wxh, const bf16* __restrict__ wxl,
        const bf16* __restrict__ whh, const bf16* __restrict__ whl, int tid) {
#pragma unroll
    for (int i = 0; i < 2; i++) {                 // h: 64 rows x 64 el per plane
        const int idx = tid + i * 256;
        const int row = idx >> 3;
        const int seg = (idx & 7) * 8;
        cp16(&s->h0Hi[buf][row][seg], h0h + (size_t)row * HID + k0 + seg);
        cp16(&s->h0Lo[buf][row][seg], h0l + (size_t)row * HID + k0 + seg);
        cp16(&s->h1Hi[buf][row][seg], h1h + (size_t)row * HID + k0 + seg);
        cp16(&s->h1Lo[buf][row][seg], h1l + (size_t)row * HID + k0 + seg);
    }
    const int row = tid >> 3;                     // w: 32 rows x 64 el per plane
    const int seg = (tid & 7) * 8;
    cp16(&s->w0Hi[buf][row][seg], w0h + (size_t)row * HID + k0 + seg);
    cp16(&s->w0Lo[buf][row][seg], w0l + (size_t)row * HID + k0 + seg);
    cp16(&s->wxHi[buf][row][seg], wxh + (size_t)row * HID + k0 + seg);
    cp16(&s->wxLo[buf][row][seg], wxl + (size_t)row * HID + k0 + seg);
    cp16(&s->whHi[buf][row][seg], whh + (size_t)row * HID + k0 + seg);
    cp16(&s->whLo[buf][row][seg], whl + (size_t)row * HID + k0 + seg);
}

__device__ __forceinline__ void mma_chunk(SmemT* s, int buf,
        float* cA, float* cB, float* cC, float* cD,
        int m0, int nsub, int gid, int tid4) {
    const uint32_t* h0H0 = (const uint32_t*)s->h0Hi[buf][m0 + gid];
    const uint32_t* h0H8 = (const uint32_t*)s->h0Hi[buf][m0 + gid + 8];
    const uint32_t* h0L0 = (const uint32_t*)s->h0Lo[buf][m0 + gid];
    const uint32_t* h0L8 = (const uint32_t*)s->h0Lo[buf][m0 + gid + 8];
    const uint32_t* h1H0 = (const uint32_t*)s->h1Hi[buf][m0 + gid];
    const uint32_t* h1H8 = (const uint32_t*)s->h1Hi[buf][m0 + gid + 8];
    const uint32_t* h1L0 = (const uint32_t*)s->h1Lo[buf][m0 + gid];
    const uint32_t* h1L8 = (const uint32_t*)s->h1Lo[buf][m0 + gid + 8];
    const uint32_t* wxHa = (const uint32_t*)s->wxHi[buf][nsub + gid];
    const uint32_t* wxHb = (const uint32_t*)s->wxHi[buf][nsub + 8 + gid];
    const uint32_t* wxLa = (const uint32_t*)s->wxLo[buf][nsub + gid];
    const uint32_t* wxLb = (const uint32_t*)s->wxLo[buf][nsub + 8 + gid];
    const uint32_t* whHa = (const uint32_t*)s->whHi[buf][nsub + gid];
    const uint32_t* whHb = (const uint32_t*)s->whHi[buf][nsub + 8 + gid];
    const uint32_t* whLa = (const uint32_t*)s->whLo[buf][nsub + gid];
    const uint32_t* whLb = (const uint32_t*)s->whLo[buf][nsub + 8 + gid];
    const uint32_t* w0Ha = (const uint32_t*)s->w0Hi[buf][nsub + gid];
    const uint32_t* w0Hb = (const uint32_t*)s->w0Hi[buf][nsub + 8 + gid];
    const uint32_t* w0La = (const uint32_t*)s->w0Lo[buf][nsub + gid];
    const uint32_t* w0Lb = (const uint32_t*)s->w0Lo[buf][nsub + 8 + gid];
#pragma unroll
    for (int kk = 0; kk < KC / 16; kk++) {
        const int w = kk * 8 + tid4;
        uint32_t a0h[4] = { h0H0[w], h0H8[w], h0H0[w + 4], h0H8[w + 4] };
        uint32_t a0l[4] = { h0L0[w], h0L8[w], h0L0[w + 4], h0L8[w + 4] };
        uint32_t a1h[4] = { h1H0[w], h1H8[w], h1H0[w + 4], h1H8[w + 4] };
        uint32_t a1l[4] = { h1L0[w], h1L8[w], h1L0[w + 4], h1L8[w + 4] };
        // G1 tile A (cols nsub..nsub+7): h0@Wx1 + h1@Wh1
        { uint32_t bh[2] = { wxHa[w], wxHa[w + 4] };
          uint32_t bl[2] = { wxLa[w], wxLa[w + 4] };
          mma_bf16(cA, a0h, bh); mma_bf16(cA, a0h, bl); mma_bf16(cA, a0l, bh); }
        { uint32_t bh[2] = { whHa[w], whHa[w + 4] };
          uint32_t bl[2] = { whLa[w], whLa[w + 4] };
          mma_bf16(cA, a1h, bh); mma_bf16(cA, a1h, bl); mma_bf16(cA, a1l, bh); }
        // G1 tile B (cols nsub+8..nsub+15)
        { uint32_t bh[2] = { wxHb[w], wxHb[w + 4] };
          uint32_t bl[2] = { wxLb[w], wxLb[w + 4] };
          mma_bf16(cB, a0h, bh); mma_bf16(cB, a0h, bl); mma_bf16(cB, a0l, bh); }
        { uint32_t bh[2] = { whHb[w], whHb[w + 4] };
          uint32_t bl[2] = { whLb[w], whLb[w + 4] };
          mma_bf16(cB, a1h, bh); mma_bf16(cB, a1h, bl); mma_bf16(cB, a1l, bh); }
        // G0-next tile C: h0@Wh0
        { uint32_t bh[2] = { w0Ha[w], w0Ha[w + 4] };
          uint32_t bl[2] = { w0La[w], w0La[w + 4] };
          mma_bf16(cC, a0h, bh); mma_bf16(cC, a0h, bl); mma_bf16(cC, a0l, bh); }
        // G0-next tile D
        { uint32_t bh[2] = { w0Hb[w], w0Hb[w + 4] };
          uint32_t bl[2] = { w0Lb[w], w0Lb[w + 4] };
          mma_bf16(cD, a0h, bh); mma_bf16(cD, a0h, bl); mma_bf16(cD, a0l, bh); }
    }
}

__global__ void __launch_bounds__(256, 1) lstm_fused(
        const float* __restrict__ b1, float* __restrict__ out) {
    SmemT* s = (SmemT*)smem_raw;
    const int tid  = threadIdx.x;
    const int lane = tid & 31;
    const int wid  = tid >> 5;
    const int gid  = lane >> 2;
    const int tid4 = lane & 3;
    const int m0   = (wid & 3) * 16;
    const int nsub = (wid >> 2) * 16;
    const int cta  = blockIdx.x;
    const int hc0  = cta * 8;

    const bf16* p0h = g_pWh0 + (size_t)cta * 2 * 32 * HID;
    const bf16* p0l = p0h + (size_t)32 * HID;
    const bf16* pxh = g_pWx1 + (size_t)cta * 2 * 32 * HID;
    const bf16* pxl = pxh + (size_t)32 * HID;
    const bf16* phh = g_pWh1 + (size_t)cta * 2 * 32 * HID;
    const bf16* phl = phh + (size_t)32 * HID;

    // ---- init: c=0, h1(-1)=0, h0(0) = act0(GX[0]) with c0=0 ----
    for (int e = tid; e < 512; e += 256) {
        const int m = e & 63, hc = e >> 6;
        s->sc1[hc][m] = 0.f;
        g_h1hi[0][m][hc0 + hc] = __float2bfloat16(0.f);
        g_h1lo[0][m][hc0 + hc] = __float2bfloat16(0.f);
        const float* gx0 = g_GX + (size_t)m * G4 + hc0 + hc;
        const float i_ = sigm(gx0[0]);
        const float cg = tanhf(gx0[2 * HID]);
        const float o_ = sigm(gx0[3 * HID]);
        const float cn = i_ * cg;                   // f*0 + i*tanh(c)
        s->sc0[hc][m] = cn;
        const float h = o_ * tanhf(cn);
        const bf16 hi = __float2bfloat16(h);
        g_h0hi[0][m][hc0 + hc] = hi;
        g_h0lo[0][m][hc0 + hc] = __float2bfloat16(h - __bfloat162float(hi));
    }
    grid_barrier();

    for (int t = 0; t < T_STEPS; t++) {
        const int rb = t & 1;
        const int wb = rb ^ 1;
        const int tn = (t + 1 < T_STEPS) ? t + 1 : T_STEPS - 1;  // clamped (t=255 result unused)

        // scalar adds: GX[t+1] for G0-half, b1 for G1-half
        float gxv[8], bv[4];
        {
            const float* gx = g_GX + (size_t)(tn * BATCH) * G4;
#pragma unroll
            for (int nt = 0; nt < 2; nt++)
#pragma unroll
                for (int j = 0; j < 4; j++) {
                    const int row = m0 + gid + ((j >> 1) << 3);
                    const int cl  = nsub + nt * 8 + 2 * tid4 + (j & 1);
                    gxv[nt * 4 + j] = gx[(size_t)row * G4 + (cl >> 3) * HID + hc0 + (cl & 7)];
                }
#pragma unroll
            for (int nt = 0; nt < 2; nt++)
#pragma unroll
                for (int d = 0; d < 2; d++) {
                    const int cl = nsub + nt * 8 + 2 * tid4 + d;
                    bv[nt * 2 + d] = b1[(cl >> 3) * HID + hc0 + (cl & 7)];
                }
        }

        float cA[4] = {0.f,0.f,0.f,0.f}, cB[4] = {0.f,0.f,0.f,0.f};
        float cC[4] = {0.f,0.f,0.f,0.f}, cD[4] = {0.f,0.f,0.f,0.f};

        // fused K=1024 pass, double-buffered
        copy_chunk(s, 0, 0, &g_h0hi[rb][0][0], &g_h0lo[rb][0][0],
                   &g_h1hi[rb][0][0], &g_h1lo[rb][0][0],
                   p0h, p0l, pxh, pxl, phh, phl, tid);
        cpcommit();
        const int NCH = HID / KC;   // 16
#pragma unroll 1
        for (int ch = 0; ch < NCH; ch++) {
            if (ch + 1 < NCH) {
                copy_chunk(s, (ch + 1) & 1, (ch + 1) * KC,
                           &g_h0hi[rb][0][0], &g_h0lo[rb][0][0],
                           &g_h1hi[rb][0][0], &g_h1lo[rb][0][0],
                           p0h, p0l, pxh, pxl, phh, phl, tid);
                cpcommit();
                cpwait1();
            } else {
                cpwait0();
            }
            __syncthreads();
            mma_chunk(s, ch & 1, cA, cB, cC, cD, m0, nsub, gid, tid4);
            __syncthreads();
        }

#pragma unroll
        for (int j = 0; j < 4; j++) {
            const int row = m0 + gid + ((j >> 1) << 3);
            const int c0  = nsub + 2 * tid4 + (j & 1);
            s->sG[row][c0]          = cA[j] + bv[j & 1];
            s->sG[row][c0 + 8]      = cB[j] + bv[2 + (j & 1)];
            s->sG[row][32 + c0]     = cC[j] + gxv[j];
            s->sG[row][32 + c0 + 8] = cD[j] + gxv[4 + j];
        }
        __syncthreads();

        // act1(t) -> h1(t);  act0(t+1) -> h0(t+1)
        for (int e = tid; e < 512; e += 256) {
            const int m = e & 63, hc = e >> 6;
            {   // layer 1, step t
                const float i_ = sigm(s->sG[m][hc]);
                const float f_ = sigm(s->sG[m][8 + hc]);
                const float cg = tanhf(s->sG[m][16 + hc]);
                const float o_ = sigm(s->sG[m][24 + hc]);
                const float cn = f_ * s->sc1[hc][m] + i_ * cg;
                s->sc1[hc][m] = cn;
                const float h = o_ * tanhf(cn);
                const bf16 hi = __float2bfloat16(h);
                const bf16 lo = __float2bfloat16(h - __bfloat162float(hi));
                g_h1hi[wb][m][hc0 + hc] = hi;
                g_h1lo[wb][m][hc0 + hc] = lo;
                g_H1hi[((size_t)t * BATCH + m) * HID + hc0 + hc] = hi;
                g_H1lo[((size_t)t * BATCH + m) * HID + hc0 + hc] = lo;
            }
            {   // layer 0, step t+1
                const float i_ = sigm(s->sG[m][32 + hc]);
                const float f_ = sigm(s->sG[m][40 + hc]);
                const float cg = tanhf(s->sG[m][48 + hc]);
                const float o_ = sigm(s->sG[m][56 + hc]);
                const float cn = f_ * s->sc0[hc][m] + i_ * cg;
                s->sc0[hc][m] = cn;
                const float h = o_ * tanhf(cn);
                const bf16 hi = __float2bfloat16(h);
                const bf16 lo = __float2bfloat16(h - __bfloat162float(hi));
                g_h0hi[wb][m][hc0 + hc] = hi;
                g_h0lo[wb][m][hc0 + hc] = lo;
            }
        }
        grid_barrier();
    }

    // ---- tail: final_h, final_c (layer 1) ----
    const int fbuf = ((T_STEPS - 1) & 1) ^ 1;
    for (int e = tid; e < 512; e += 256) {
        const int m = e & 63, hc = e >> 6;
        const size_t off = (size_t)MB * DOUT;
        const float h = __bfloat162float(g_h1hi[fbuf][m][hc0 + hc]) +
                        __bfloat162float(g_h1lo[fbuf][m][hc0 + hc]);
        out[off + (size_t)m * HID + hc0 + hc] = h;
        out[off + (size_t)BATCH * HID + (size_t)m * HID + hc0 + hc] = s->sc1[hc][m];
    }
}

// ======================= big tensor-core GEMM ===============================
#define GBK 32
struct GSmem {
    alignas(16) bf16 aHi[2][128][GBK + 8];
    alignas(16) bf16 aLo[2][128][GBK + 8];
    alignas(16) bf16 bHi[2][128][GBK + 8];
    alignas(16) bf16 bLo[2][128][GBK + 8];
};

__device__ __forceinline__ void g_copy(GSmem* s, int buf, int k0,
        const bf16* __restrict__ AHi, const bf16* __restrict__ ALo,
        const bf16* __restrict__ BHi, const bf16* __restrict__ BLo,
        int K, int rowA, int rowB, int tid) {
#pragma unroll
    for (int i = 0; i < 2; i++) {
        const int idx = tid + i * 256;
        const int row = idx >> 2;
        const int seg = (idx & 3) * 8;
        cp16(&s->aHi[buf][row][seg], AHi + (size_t)(rowA + row) * K + k0 + seg);
        cp16(&s->aLo[buf][row][seg], ALo + (size_t)(rowA + row) * K + k0 + seg);
        cp16(&s->bHi[buf][row][seg], BHi + (size_t)(rowB + row) * K + k0 + seg);
        cp16(&s->bLo[buf][row][seg], BLo + (size_t)(rowB + row) * K + k0 + seg);
    }
}

__global__ void __launch_bounds__(256, 1) gemm_mma_big(
        const bf16* __restrict__ AHi, const bf16* __restrict__ ALo,
        const bf16* __restrict__ BHi, const bf16* __restrict__ BLo,
        const float* __restrict__ bias, float* __restrict__ C,
        int M, int N, int K) {
    GSmem* s = (GSmem*)smem_raw;
    const int tid  = threadIdx.x;
    const int lane = tid & 31;
    const int wid  = tid >> 5;
    const int gid  = lane >> 2;
    const int tid4 = lane & 3;
    const int m0w  = (wid & 1) * 64;
    const int n0w  = (wid >> 1) * 32;
    const int rowA = blockIdx.y * 128;
    const int rowB = blockIdx.x * 128;

    float acc[4][4][4];
#pragma unroll
    for (int a = 0; a < 4; a++)
#pragma unroll
        for (int b = 0; b < 4; b++)
#pragma unroll
            for (int c = 0; c < 4; c++) acc[a][b][c] = 0.f;

    g_copy(s, 0, 0, AHi, ALo, BHi, BLo, K, rowA, rowB, tid);
    cpcommit();
    const int NCH = K / GBK;
#pragma unroll 1
    for (int ch = 0; ch < NCH; ch++) {
        if (ch + 1 < NCH) {
            g_copy(s, (ch + 1) & 1, (ch + 1) * GBK, AHi, ALo, BHi, BLo, K, rowA, rowB, tid);
            cpcommit();
            cpwait1();
        } else {
            cpwait0();
        }
        __syncthreads();
        const int buf = ch & 1;
#pragma unroll
        for (int kk = 0; kk < GBK / 16; kk++) {
            const int w = kk * 8 + tid4;
#pragma unroll
            for (int mt = 0; mt < 4; mt++) {
                const uint32_t* aH0 = (const uint32_t*)s->aHi[buf][m0w + mt * 16 + gid];
                const uint32_t* aH8 = (const uint32_t*)s->aHi[buf][m0w + mt * 16 + gid + 8];
                const uint32_t* aL0 = (const uint32_t*)s->aLo[buf][m0w + mt * 16 + gid];
                const uint32_t* aL8 = (const uint32_t*)s->aLo[buf][m0w + mt * 16 + gid + 8];
                uint32_t ah[4] = { aH0[w], aH8[w], aH0[w + 4], aH8[w + 4] };
                uint32_t al[4] = { aL0[w], aL8[w], aL0[w + 4], aL8[w + 4] };
#pragma unroll
                for (int nt = 0; nt < 4; nt++) {
                    const uint32_t* bH = (const uint32_t*)s->bHi[buf][n0w + nt * 8 + gid];
                    const uint32_t* bL = (const uint32_t*)s->bLo[buf][n0w + nt * 8 + gid];
                    uint32_t bh[2] = { bH[w], bH[w + 4] };
                    uint32_t bl[2] = { bL[w], bL[w + 4] };
                    mma_bf16(acc[mt][nt], ah, bh);
                    mma_bf16(acc[mt][nt], ah, bl);
                    mma_bf16(acc[mt][nt], al, bh);
                }
            }
        }
        __syncthreads();
    }

#pragma unroll
    for (int mt = 0; mt < 4; mt++)
#pragma unroll
        for (int nt = 0; nt < 4; nt++)
#pragma unroll
            for (int j = 0; j < 4; j++) {
                const int r = rowA + m0w + mt * 16 + gid + ((j >> 1) << 3);
                const int c = rowB + n0w + nt * 8 + 2 * tid4 + (j & 1);
                C[(size_t)r * N + c] = acc[mt][nt][j] + bias[c];
            }
}

// ======================= packing kernels ====================================
__global__ __launch_bounds__(256) void split_rows(const float* __restrict__ src,
        bf16* __restrict__ hi, bf16* __restrict__ lo, size_t n) {
    for (size_t i = (size_t)blockIdx.x * blockDim.x + threadIdx.x;
         i < n; i += (size_t)gridDim.x * blockDim.x) {
        const float v = src[i];
        const bf16 h = __float2bfloat16(v);
        hi[i] = h;
        lo[i] = __float2bfloat16(v - __bfloat162float(h));
    }
}

__global__ __launch_bounds__(256) void split_transpose(const float* __restrict__ src,
        bf16* __restrict__ hi, bf16* __restrict__ lo, int K, int N) {
    const size_t total = (size_t)K * N;
    for (size_t i = (size_t)blockIdx.x * blockDim.x + threadIdx.x;
         i < total; i += (size_t)gridDim.x * blockDim.x) {
        const int n = (int)(i / K);
        const int k = (int)(i % K);
        const float v = src[(size_t)k * N + n];
        const bf16 h = __float2bfloat16(v);
        hi[i] = h;
        lo[i] = __float2bfloat16(v - __bfloat162float(h));
    }
}

__global__ __launch_bounds__(256) void pack_w_bf16(const float* __restrict__ W,
                                                   bf16* __restrict__ P) {
    const size_t total = (size_t)NCTA * 32 * HID;
    for (size_t idx = (size_t)blockIdx.x * blockDim.x + threadIdx.x;
         idx < total; idx += (size_t)gridDim.x * blockDim.x) {
        const int cta = (int)(idx >> 15);
        const int n   = (int)((idx >> 10) & 31);
        const int k   = (int)(idx & 1023);
        const int gcol = (n >> 3) * HID + cta * 8 + (n & 7);
        const float w = W[(size_t)k * G4 + gcol];
        const bf16 hi = __float2bfloat16(w);
        const bf16 lo = __float2bfloat16(w - __bfloat162float(hi));
        const size_t base = (size_t)cta * 2 * 32 * HID;
        P[base + (size_t)n * HID + k] = hi;
        P[base + (size_t)32 * HID + (size_t)n * HID + k] = lo;
    }
}

// ---------------- launch ----------------------------------------------------
extern "C" void kernel_launch(void* const* d_in, const int* in_sizes, int n_in,
                              void* d_out, int out_size) {
    const float* inputs = (const float*)d_in[0];
    const float* Wx0    = (const float*)d_in[1];
    const float* Wh0    = (const float*)d_in[2];
    const float* b0     = (const float*)d_in[3];
    const float* Wx1    = (const float*)d_in[4];
    const float* Wh1    = (const float*)d_in[5];
    const float* b1     = (const float*)d_in[6];
    const float* Wout   = (const float*)d_in[7];
    const float* bout   = (const float*)d_in[8];
    float* out = (float*)d_out;

    float *pGX;
    bf16 *pp0, *pp1, *pp2, *pinH, *pinL, *pWx0h, *pWx0l, *pWoh, *pWol, *pH1h, *pH1l;
    cudaGetSymbolAddress((void**)&pGX,   g_GX);
    cudaGetSymbolAddress((void**)&pp0,   g_pWh0);
    cudaGetSymbolAddress((void**)&pp1,   g_pWx1);
    cudaGetSymbolAddress((void**)&pp2,   g_pWh1);
    cudaGetSymbolAddress((void**)&pinH,  g_inHi);
    cudaGetSymbolAddress((void**)&pinL,  g_inLo);
    cudaGetSymbolAddress((void**)&pWx0h, g_Wx0Thi);
    cudaGetSymbolAddress((void**)&pWx0l, g_Wx0Tlo);
    cudaGetSymbolAddress((void**)&pWoh,  g_WoutThi);
    cudaGetSymbolAddress((void**)&pWol,  g_WoutTlo);
    cudaGetSymbolAddress((void**)&pH1h,  g_H1hi);
    cudaGetSymbolAddress((void**)&pH1l,  g_H1lo);

    cudaFuncSetAttribute(lstm_fused, cudaFuncAttributeMaxDynamicSharedMemorySize,
                         (int)sizeof(SmemT));
    cudaFuncSetAttribute(gemm_mma_big, cudaFuncAttributeMaxDynamicSharedMemorySize,
                         (int)sizeof(GSmem));

    // 0) packing / splitting
    pack_w_bf16<<<1024, 256>>>(Wh0, pp0);
    pack_w_bf16<<<1024, 256>>>(Wx1, pp1);
    pack_w_bf16<<<1024, 256>>>(Wh1, pp2);
    split_rows<<<2048, 256>>>(inputs, pinH, pinL, (size_t)MB * DIN);
    split_transpose<<<1024, 256>>>(Wx0, pWx0h, pWx0l, DIN, G4);
    split_transpose<<<512, 256>>>(Wout, pWoh, pWol, HID, DOUT);

    // 1) GX = inputs @ Wx0 + b0   (tensor cores)
    gemm_mma_big<<<dim3(G4 / 128, MB / 128), 256, sizeof(GSmem)>>>(
        pinH, pinL, pWx0h, pWx0l, b0, pGX, MB, G4, DIN);

    // 2) fused 256-step recurrence (one barrier per step)
    lstm_fused<<<NCTA, 256, sizeof(SmemT)>>>(b1, out);

    // 3) outs = H1_all @ Wout + bout  (tensor cores)
    gemm_mma_big<<<dim3(DOUT / 128, MB / 128), 256, sizeof(GSmem)>>>(
        pH1h, pH1l, pWoh, pWol, bout, out, MB, DOUT, HID);
}

// round 12
// speedup vs baseline: 11.1685x; 1.0632x over previous
#include <cuda_runtime.h>
#include <cuda_bf16.h>
#include <math.h>
#include <stdint.h>
#include <stddef.h>

#define T_STEPS 256
#define BATCH   64
#define DIN     512
#define HID     1024
#define DOUT    512
#define G4      (4*HID)          /* 4096 */
#define MB      (T_STEPS*BATCH)  /* 16384 */
#define NCTA    128
#define KC      64               /* k-chunk */
#define KR      72               /* padded bf16 row */
#define NCH     (HID/KC)         /* 16 chunks */

typedef __nv_bfloat16 bf16;

// ---------------- scratch (device globals; no runtime allocation) ----------
__device__ __align__(16) float g_GX[(size_t)MB * G4];
__device__ __align__(16) bf16  g_inHi[(size_t)MB * DIN];
__device__ __align__(16) bf16  g_inLo[(size_t)MB * DIN];
__device__ __align__(16) bf16  g_Wx0Thi[(size_t)G4 * DIN];
__device__ __align__(16) bf16  g_Wx0Tlo[(size_t)G4 * DIN];
__device__ __align__(16) bf16  g_WoutThi[(size_t)DOUT * HID];
__device__ __align__(16) bf16  g_WoutTlo[(size_t)DOUT * HID];
__device__ __align__(16) bf16  g_H1hi[(size_t)MB * HID];
__device__ __align__(16) bf16  g_H1lo[(size_t)MB * HID];
__device__ __align__(16) bf16  g_h0hi[2][BATCH][HID];
__device__ __align__(16) bf16  g_h0lo[2][BATCH][HID];
__device__ __align__(16) bf16  g_h1hi[2][BATCH][HID];
__device__ __align__(16) bf16  g_h1lo[2][BATCH][HID];
__device__ __align__(16) bf16  g_pWh0[(size_t)NCTA * 2 * 32 * HID];
__device__ __align__(16) bf16  g_pWx1[(size_t)NCTA * 2 * 32 * HID];
__device__ __align__(16) bf16  g_pWh1[(size_t)NCTA * 2 * 32 * HID];
__device__ unsigned g_grp[16];
__device__ unsigned g_bar_count = 0;
__device__ unsigned g_bar_gen   = 0;

__device__ __forceinline__ float sigm(float x) { return 1.0f / (1.0f + expf(-x)); }

// ---------------- async copy helpers ---------------------------------------
__device__ __forceinline__ void cp16(void* dst, const void* src) {
    uint32_t d = (uint32_t)__cvta_generic_to_shared(dst);
    asm volatile("cp.async.cg.shared.global [%0], [%1], 16;" :: "r"(d), "l"(src));
}
__device__ __forceinline__ void cpcommit() { asm volatile("cp.async.commit_group;"); }
__device__ __forceinline__ void cpwait2()  { asm volatile("cp.async.wait_group 2;"); }
__device__ __forceinline__ void cpwait1()  { asm volatile("cp.async.wait_group 1;"); }
__device__ __forceinline__ void cpwait0()  { asm volatile("cp.async.wait_group 0;"); }

// ---------------- mma ------------------------------------------------------
__device__ __forceinline__ void mma_bf16(float* c, const uint32_t* a, const uint32_t* b) {
    asm volatile(
        "mma.sync.aligned.m16n8k16.row.col.f32.bf16.bf16.f32 "
        "{%0,%1,%2,%3}, {%4,%5,%6,%7}, {%8,%9}, {%0,%1,%2,%3};\n"
        : "+f"(c[0]), "+f"(c[1]), "+f"(c[2]), "+f"(c[3])
        : "r"(a[0]), "r"(a[1]), "r"(a[2]), "r"(a[3]), "r"(b[0]), "r"(b[1]));
}

extern __shared__ char smem_raw[];

// ======================= fused persistent recurrence ========================
struct SmemT {
    alignas(16) bf16  h0Hi[3][BATCH][KR];
    alignas(16) bf16  h0Lo[3][BATCH][KR];
    alignas(16) bf16  h1Hi[3][BATCH][KR];
    alignas(16) bf16  h1Lo[3][BATCH][KR];
    alignas(16) bf16  w0Hi[3][32][KR];   // Wh0
    alignas(16) bf16  w0Lo[3][32][KR];
    alignas(16) bf16  wxHi[3][32][KR];   // Wx1
    alignas(16) bf16  wxLo[3][32][KR];
    alignas(16) bf16  whHi[3][32][KR];   // Wh1
    alignas(16) bf16  whLo[3][32][KR];
    alignas(16) float sG[BATCH][68];
    alignas(16) float sc0[8][BATCH];
    alignas(16) float sc1[8][BATCH];
};

__device__ __forceinline__ void copy_h(SmemT* s, int buf, int k0,
        const bf16* __restrict__ h0h, const bf16* __restrict__ h0l,
        const bf16* __restrict__ h1h, const bf16* __restrict__ h1l, int tid) {
#pragma unroll
    for (int i = 0; i < 2; i++) {
        const int idx = tid + i * 256;
        const int row = idx >> 3;
        const int seg = (idx & 7) * 8;
        cp16(&s->h0Hi[buf][row][seg], h0h + (size_t)row * HID + k0 + seg);
        cp16(&s->h0Lo[buf][row][seg], h0l + (size_t)row * HID + k0 + seg);
        cp16(&s->h1Hi[buf][row][seg], h1h + (size_t)row * HID + k0 + seg);
        cp16(&s->h1Lo[buf][row][seg], h1l + (size_t)row * HID + k0 + seg);
    }
}

__device__ __forceinline__ void copy_w(SmemT* s, int buf, int k0,
        const bf16* __restrict__ w0h, const bf16* __restrict__ w0l,
        const bf16* __restrict__ wxh, const bf16* __restrict__ wxl,
        const bf16* __restrict__ whh, const bf16* __restrict__ whl, int tid) {
    const int row = tid >> 3;            // 0..31
    const int seg = (tid & 7) * 8;
    cp16(&s->w0Hi[buf][row][seg], w0h + (size_t)row * HID + k0 + seg);
    cp16(&s->w0Lo[buf][row][seg], w0l + (size_t)row * HID + k0 + seg);
    cp16(&s->wxHi[buf][row][seg], wxh + (size_t)row * HID + k0 + seg);
    cp16(&s->wxLo[buf][row][seg], wxl + (size_t)row * HID + k0 + seg);
    cp16(&s->whHi[buf][row][seg], whh + (size_t)row * HID + k0 + seg);
    cp16(&s->whLo[buf][row][seg], whl + (size_t)row * HID + k0 + seg);
}

__device__ __forceinline__ void mma_chunk(SmemT* s, int buf,
        float* cA, float* cB, float* cC, float* cD,
        int m0, int nsub, int gid, int tid4) {
    const uint32_t* h0H0 = (const uint32_t*)s->h0Hi[buf][m0 + gid];
    const uint32_t* h0H8 = (const uint32_t*)s->h0Hi[buf][m0 + gid + 8];
    const uint32_t* h0L0 = (const uint32_t*)s->h0Lo[buf][m0 + gid];
    const uint32_t* h0L8 = (const uint32_t*)s->h0Lo[buf][m0 + gid + 8];
    const uint32_t* h1H0 = (const uint32_t*)s->h1Hi[buf][m0 + gid];
    const uint32_t* h1H8 = (const uint32_t*)s->h1Hi[buf][m0 + gid + 8];
    const uint32_t* h1L0 = (const uint32_t*)s->h1Lo[buf][m0 + gid];
    const uint32_t* h1L8 = (const uint32_t*)s->h1Lo[buf][m0 + gid + 8];
    const uint32_t* wxHa = (const uint32_t*)s->wxHi[buf][nsub + gid];
    const uint32_t* wxHb = (const uint32_t*)s->wxHi[buf][nsub + 8 + gid];
    const uint32_t* wxLa = (const uint32_t*)s->wxLo[buf][nsub + gid];
    const uint32_t* wxLb = (const uint32_t*)s->wxLo[buf][nsub + 8 + gid];
    const uint32_t* whHa = (const uint32_t*)s->whHi[buf][nsub + gid];
    const uint32_t* whHb = (const uint32_t*)s->whHi[buf][nsub + 8 + gid];
    const uint32_t* whLa = (const uint32_t*)s->whLo[buf][nsub + gid];
    const uint32_t* whLb = (const uint32_t*)s->whLo[buf][nsub + 8 + gid];
    const uint32_t* w0Ha = (const uint32_t*)s->w0Hi[buf][nsub + gid];
    const uint32_t* w0Hb = (const uint32_t*)s->w0Hi[buf][nsub + 8 + gid];
    const uint32_t* w0La = (const uint32_t*)s->w0Lo[buf][nsub + gid];
    const uint32_t* w0Lb = (const uint32_t*)s->w0Lo[buf][nsub + 8 + gid];
#pragma unroll
    for (int kk = 0; kk < KC / 16; kk++) {
        const int w = kk * 8 + tid4;
        uint32_t a0h[4] = { h0H0[w], h0H8[w], h0H0[w + 4], h0H8[w + 4] };
        uint32_t a0l[4] = { h0L0[w], h0L8[w], h0L0[w + 4], h0L8[w + 4] };
        uint32_t a1h[4] = { h1H0[w], h1H8[w], h1H0[w + 4], h1H8[w + 4] };
        uint32_t a1l[4] = { h1L0[w], h1L8[w], h1L0[w + 4], h1L8[w + 4] };
        { uint32_t bh[2] = { wxHa[w], wxHa[w + 4] };
          uint32_t bl[2] = { wxLa[w], wxLa[w + 4] };
          mma_bf16(cA, a0h, bh); mma_bf16(cA, a0h, bl); mma_bf16(cA, a0l, bh); }
        { uint32_t bh[2] = { whHa[w], whHa[w + 4] };
          uint32_t bl[2] = { whLa[w], whLa[w + 4] };
          mma_bf16(cA, a1h, bh); mma_bf16(cA, a1h, bl); mma_bf16(cA, a1l, bh); }
        { uint32_t bh[2] = { wxHb[w], wxHb[w + 4] };
          uint32_t bl[2] = { wxLb[w], wxLb[w + 4] };
          mma_bf16(cB, a0h, bh); mma_bf16(cB, a0h, bl); mma_bf16(cB, a0l, bh); }
        { uint32_t bh[2] = { whHb[w], whHb[w + 4] };
          uint32_t bl[2] = { whLb[w], whLb[w + 4] };
          mma_bf16(cB, a1h, bh); mma_bf16(cB, a1h, bl); mma_bf16(cB, a1l, bh); }
        { uint32_t bh[2] = { w0Ha[w], w0Ha[w + 4] };
          uint32_t bl[2] = { w0La[w], w0La[w + 4] };
          mma_bf16(cC, a0h, bh); mma_bf16(cC, a0h, bl); mma_bf16(cC, a0l, bh); }
        { uint32_t bh[2] = { w0Hb[w], w0Hb[w + 4] };
          uint32_t bl[2] = { w0Lb[w], w0Lb[w + 4] };
          mma_bf16(cD, a0h, bh); mma_bf16(cD, a0h, bl); mma_bf16(cD, a0l, bh); }
    }
}

__global__ void __launch_bounds__(256, 1) lstm_fused(
        const float* __restrict__ b1, float* __restrict__ out) {
    SmemT* s = (SmemT*)smem_raw;
    const int tid  = threadIdx.x;
    const int lane = tid & 31;
    const int wid  = tid >> 5;
    const int gid  = lane >> 2;
    const int tid4 = lane & 3;
    const int m0   = (wid & 3) * 16;
    const int nsub = (wid >> 2) * 16;
    const int cta  = blockIdx.x;
    const int hc0  = cta * 8;
    const int am   = tid >> 2;          // act row 0..63
    const int ac   = (tid & 3) * 2;     // act col pair 0,2,4,6

    const bf16* p0h = g_pWh0 + (size_t)cta * 2 * 32 * HID;
    const bf16* p0l = p0h + (size_t)32 * HID;
    const bf16* pxh = g_pWx1 + (size_t)cta * 2 * 32 * HID;
    const bf16* pxl = pxh + (size_t)32 * HID;
    const bf16* phh = g_pWh1 + (size_t)cta * 2 * 32 * HID;
    const bf16* phl = phh + (size_t)32 * HID;

    // ---- init: c=0, h1(-1)=0, h0(0) = act0(GX[0]) with c=0 ----
    for (int e = tid; e < 512; e += 256) {
        const int m = e & 63, hc = e >> 6;
        s->sc1[hc][m] = 0.f;
        g_h1hi[0][m][hc0 + hc] = __float2bfloat16(0.f);
        g_h1lo[0][m][hc0 + hc] = __float2bfloat16(0.f);
        const float* gx0 = g_GX + (size_t)m * G4 + hc0 + hc;
        const float i_ = sigm(gx0[0]);
        const float cg = tanhf(gx0[2 * HID]);
        const float o_ = sigm(gx0[3 * HID]);
        const float cn = i_ * cg;
        s->sc0[hc][m] = cn;
        const float h = o_ * tanhf(cn);
        const bf16 hi = __float2bfloat16(h);
        g_h0hi[0][m][hc0 + hc] = hi;
        g_h0lo[0][m][hc0 + hc] = __float2bfloat16(h - __bfloat162float(hi));
    }

    // bias (constant across steps)
    float bv[4];
#pragma unroll
    for (int nt = 0; nt < 2; nt++)
#pragma unroll
        for (int d = 0; d < 2; d++) {
            const int cl = nsub + nt * 8 + 2 * tid4 + d;
            bv[nt * 2 + d] = b1[(cl >> 3) * HID + hc0 + (cl & 7)];
        }

    // pre-barrier weight prefetch for chunks 0,1 (weights immutable)
    copy_w(s, 0, 0,  p0h, p0l, pxh, pxl, phh, phl, tid); cpcommit();
    copy_w(s, 1, KC, p0h, p0l, pxh, pxl, phh, phl, tid); cpcommit();

    // initial grid barrier (h0(0)/h1(-1) must be globally visible)
    __threadfence();
    __syncthreads();
    if (tid == 0) {
        unsigned gen = *(volatile unsigned*)&g_bar_gen;
        if ((atomicAdd(&g_grp[cta >> 3], 1u) & 7u) == 7u)
            if ((atomicAdd(&g_bar_count, 1u) & 15u) == 15u) {
                __threadfence();
                *(volatile unsigned*)&g_bar_gen = gen + 1;
            }
        while (*(volatile unsigned*)&g_bar_gen == gen) { __nanosleep(20); }
    }
    // gxv for step 0 (GX[1]) overlaps tid0's spin
    float gxv[8];
    {
        const float* gx = g_GX + (size_t)BATCH * G4;
#pragma unroll
        for (int nt = 0; nt < 2; nt++)
#pragma unroll
            for (int j = 0; j < 4; j++) {
                const int row = m0 + gid + ((j >> 1) << 3);
                const int cl  = nsub + nt * 8 + 2 * tid4 + (j & 1);
                gxv[nt * 4 + j] = gx[(size_t)row * G4 + (cl >> 3) * HID + hc0 + (cl & 7)];
            }
    }
    __syncthreads();
    copy_h(s, 0, 0,  &g_h0hi[0][0][0], &g_h0lo[0][0][0],
           &g_h1hi[0][0][0], &g_h1lo[0][0][0], tid); cpcommit();
    copy_h(s, 1, KC, &g_h0hi[0][0][0], &g_h0lo[0][0][0],
           &g_h1hi[0][0][0], &g_h1lo[0][0][0], tid); cpcommit();

    for (int t = 0; t < T_STEPS; t++) {
        const int rb = t & 1;
        const int wb = rb ^ 1;

        float cA[4] = {0.f,0.f,0.f,0.f}, cB[4] = {0.f,0.f,0.f,0.f};
        float cC[4] = {0.f,0.f,0.f,0.f}, cD[4] = {0.f,0.f,0.f,0.f};

#pragma unroll 1
        for (int ch = 0; ch < NCH; ch++) {
            if (ch < NCH - 2) {
                const int nb = (ch + 2) % 3;
                const int k0 = (ch + 2) * KC;
                copy_w(s, nb, k0, p0h, p0l, pxh, pxl, phh, phl, tid);
                copy_h(s, nb, k0, &g_h0hi[rb][0][0], &g_h0lo[rb][0][0],
                       &g_h1hi[rb][0][0], &g_h1lo[rb][0][0], tid);
                cpcommit();
                cpwait2();
            } else if (ch == NCH - 2) {
                cpwait1();
            } else {
                cpwait0();
            }
            __syncthreads();
            mma_chunk(s, ch % 3, cA, cB, cC, cD, m0, nsub, gid, tid4);
            __syncthreads();
        }

#pragma unroll
        for (int j = 0; j < 4; j++) {
            const int row = m0 + gid + ((j >> 1) << 3);
            const int c0  = nsub + 2 * tid4 + (j & 1);
            s->sG[row][c0]          = cA[j] + bv[j & 1];
            s->sG[row][c0 + 8]      = cB[j] + bv[2 + (j & 1)];
            s->sG[row][32 + c0]     = cC[j] + gxv[j];
            s->sG[row][32 + c0 + 8] = cD[j] + gxv[4 + j];
        }
        // weight prefetch for next step's chunks 0,1 (all staging drained at ch=15)
        if (t + 1 < T_STEPS) {
            copy_w(s, 0, 0,  p0h, p0l, pxh, pxl, phh, phl, tid); cpcommit();
            copy_w(s, 1, KC, p0h, p0l, pxh, pxl, phh, phl, tid); cpcommit();
        }
        __syncthreads();   // sG visible

        // ---- act: layer1 step t, layer0 step t+1 (2 cols per thread, 4B stores) ----
        {
            // layer 1
            float i0 = sigm(s->sG[am][ac]),      i1 = sigm(s->sG[am][ac + 1]);
            float f0 = sigm(s->sG[am][8 + ac]),  f1 = sigm(s->sG[am][8 + ac + 1]);
            float g0 = tanhf(s->sG[am][16 + ac]),g1 = tanhf(s->sG[am][16 + ac + 1]);
            float o0 = sigm(s->sG[am][24 + ac]), o1 = sigm(s->sG[am][24 + ac + 1]);
            float c0n = f0 * s->sc1[ac][am]     + i0 * g0;
            float c1n = f1 * s->sc1[ac + 1][am] + i1 * g1;
            s->sc1[ac][am] = c0n;  s->sc1[ac + 1][am] = c1n;
            float h0v = o0 * tanhf(c0n), h1v = o1 * tanhf(c1n);
            bf16 h0hiB = __float2bfloat16(h0v);
            bf16 h1hiB = __float2bfloat16(h1v);
            bf16 h0loB = __float2bfloat16(h0v - __bfloat162float(h0hiB));
            bf16 h1loB = __float2bfloat16(h1v - __bfloat162float(h1hiB));
            __nv_bfloat162 phi; phi.x = h0hiB; phi.y = h1hiB;
            __nv_bfloat162 plo; plo.x = h0loB; plo.y = h1loB;
            *(__nv_bfloat162*)&g_h1hi[wb][am][hc0 + ac] = phi;
            *(__nv_bfloat162*)&g_h1lo[wb][am][hc0 + ac] = plo;
            *(__nv_bfloat162*)&g_H1hi[((size_t)t * BATCH + am) * HID + hc0 + ac] = phi;
            *(__nv_bfloat162*)&g_H1lo[((size_t)t * BATCH + am) * HID + hc0 + ac] = plo;
        }
        {
            // layer 0 (step t+1)
            float i0 = sigm(s->sG[am][32 + ac]),      i1 = sigm(s->sG[am][32 + ac + 1]);
            float f0 = sigm(s->sG[am][40 + ac]),      f1 = sigm(s->sG[am][40 + ac + 1]);
            float g0 = tanhf(s->sG[am][48 + ac]),     g1 = tanhf(s->sG[am][48 + ac + 1]);
            float o0 = sigm(s->sG[am][56 + ac]),      o1 = sigm(s->sG[am][56 + ac + 1]);
            float c0n = f0 * s->sc0[ac][am]     + i0 * g0;
            float c1n = f1 * s->sc0[ac + 1][am] + i1 * g1;
            s->sc0[ac][am] = c0n;  s->sc0[ac + 1][am] = c1n;
            float h0v = o0 * tanhf(c0n), h1v = o1 * tanhf(c1n);
            bf16 h0hiB = __float2bfloat16(h0v);
            bf16 h1hiB = __float2bfloat16(h1v);
            bf16 h0loB = __float2bfloat16(h0v - __bfloat162float(h0hiB));
            bf16 h1loB = __float2bfloat16(h1v - __bfloat162float(h1hiB));
            __nv_bfloat162 phi; phi.x = h0hiB; phi.y = h1hiB;
            __nv_bfloat162 plo; plo.x = h0loB; plo.y = h1loB;
            *(__nv_bfloat162*)&g_h0hi[wb][am][hc0 + ac] = phi;
            *(__nv_bfloat162*)&g_h0lo[wb][am][hc0 + ac] = plo;
        }

        if (t + 1 >= T_STEPS) break;   // last step: no barrier / prefetch needed

        __threadfence();
        __syncthreads();
        if (tid == 0) {
            unsigned gen = *(volatile unsigned*)&g_bar_gen;
            if ((atomicAdd(&g_grp[cta >> 3], 1u) & 7u) == 7u)
                if ((atomicAdd(&g_bar_count, 1u) & 15u) == 15u) {
                    __threadfence();
                    *(volatile unsigned*)&g_bar_gen = gen + 1;
                }
            while (*(volatile unsigned*)&g_bar_gen == gen) { __nanosleep(20); }
        }
        // load gxv for step t+1 (GX immutable) — overlaps tid0's spin
        if (t + 2 < T_STEPS + 1) {
            const int tn = (t + 2 < T_STEPS) ? t + 2 : T_STEPS - 1;
            const float* gx = g_GX + (size_t)(tn * BATCH) * G4;
#pragma unroll
            for (int nt = 0; nt < 2; nt++)
#pragma unroll
                for (int j = 0; j < 4; j++) {
                    const int row = m0 + gid + ((j >> 1) << 3);
                    const int cl  = nsub + nt * 8 + 2 * tid4 + (j & 1);
                    gxv[nt * 4 + j] = gx[(size_t)row * G4 + (cl >> 3) * HID + hc0 + (cl & 7)];
                }
        }
        __syncthreads();
        // h prefetch for next step's chunks 0,1 (reads h[wb] just published)
        copy_h(s, 0, 0,  &g_h0hi[wb][0][0], &g_h0lo[wb][0][0],
               &g_h1hi[wb][0][0], &g_h1lo[wb][0][0], tid); cpcommit();
        copy_h(s, 1, KC, &g_h0hi[wb][0][0], &g_h0lo[wb][0][0],
               &g_h1hi[wb][0][0], &g_h1lo[wb][0][0], tid); cpcommit();
    }

    // ---- tail: final_h, final_c (layer 1) ----
    __syncthreads();
    const int fbuf = ((T_STEPS - 1) & 1) ^ 1;
    for (int e = tid; e < 512; e += 256) {
        const int m = e & 63, hc = e >> 6;
        const size_t off = (size_t)MB * DOUT;
        const float h = __bfloat162float(g_h1hi[fbuf][m][hc0 + hc]) +
                        __bfloat162float(g_h1lo[fbuf][m][hc0 + hc]);
        out[off + (size_t)m * HID + hc0 + hc] = h;
        out[off + (size_t)BATCH * HID + (size_t)m * HID + hc0 + hc] = s->sc1[hc][m];
    }
}

// ======================= big tensor-core GEMM ===============================
#define GBK 32
struct GSmem {
    alignas(16) bf16 aHi[2][128][GBK + 8];
    alignas(16) bf16 aLo[2][128][GBK + 8];
    alignas(16) bf16 bHi[2][128][GBK + 8];
    alignas(16) bf16 bLo[2][128][GBK + 8];
};

__device__ __forceinline__ void g_copy(GSmem* s, int buf, int k0,
        const bf16* __restrict__ AHi, const bf16* __restrict__ ALo,
        const bf16* __restrict__ BHi, const bf16* __restrict__ BLo,
        int K, int rowA, int rowB, int tid) {
#pragma unroll
    for (int i = 0; i < 2; i++) {
        const int idx = tid + i * 256;
        const int row = idx >> 2;
        const int seg = (idx & 3) * 8;
        cp16(&s->aHi[buf][row][seg], AHi + (size_t)(rowA + row) * K + k0 + seg);
        cp16(&s->aLo[buf][row][seg], ALo + (size_t)(rowA + row) * K + k0 + seg);
        cp16(&s->bHi[buf][row][seg], BHi + (size_t)(rowB + row) * K + k0 + seg);
        cp16(&s->bLo[buf][row][seg], BLo + (size_t)(rowB + row) * K + k0 + seg);
    }
}

__global__ void __launch_bounds__(256, 1) gemm_mma_big(
        const bf16* __restrict__ AHi, const bf16* __restrict__ ALo,
        const bf16* __restrict__ BHi, const bf16* __restrict__ BLo,
        const float* __restrict__ bias, float* __restrict__ C,
        int M, int N, int K) {
    GSmem* s = (GSmem*)smem_raw;
    const int tid  = threadIdx.x;
    const int lane = tid & 31;
    const int wid  = tid >> 5;
    const int gid  = lane >> 2;
    const int tid4 = lane & 3;
    const int m0w  = (wid & 1) * 64;
    const int n0w  = (wid >> 1) * 32;
    const int rowA = blockIdx.y * 128;
    const int rowB = blockIdx.x * 128;

    float acc[4][4][4];
#pragma unroll
    for (int a = 0; a < 4; a++)
#pragma unroll
        for (int b = 0; b < 4; b++)
#pragma unroll
            for (int c = 0; c < 4; c++) acc[a][b][c] = 0.f;

    g_copy(s, 0, 0, AHi, ALo, BHi, BLo, K, rowA, rowB, tid);
    cpcommit();
    const int NCHg = K / GBK;
#pragma unroll 1
    for (int ch = 0; ch < NCHg; ch++) {
        if (ch + 1 < NCHg) {
            g_copy(s, (ch + 1) & 1, (ch + 1) * GBK, AHi, ALo, BHi, BLo, K, rowA, rowB, tid);
            cpcommit();
            cpwait1();
        } else {
            cpwait0();
        }
        __syncthreads();
        const int buf = ch & 1;
#pragma unroll
        for (int kk = 0; kk < GBK / 16; kk++) {
            const int w = kk * 8 + tid4;
#pragma unroll
            for (int mt = 0; mt < 4; mt++) {
                const uint32_t* aH0 = (const uint32_t*)s->aHi[buf][m0w + mt * 16 + gid];
                const uint32_t* aH8 = (const uint32_t*)s->aHi[buf][m0w + mt * 16 + gid + 8];
                const uint32_t* aL0 = (const uint32_t*)s->aLo[buf][m0w + mt * 16 + gid];
                const uint32_t* aL8 = (const uint32_t*)s->aLo[buf][m0w + mt * 16 + gid + 8];
                uint32_t ah[4] = { aH0[w], aH8[w], aH0[w + 4], aH8[w + 4] };
                uint32_t al[4] = { aL0[w], aL8[w], aL0[w + 4], aL8[w + 4] };
#pragma unroll
                for (int nt = 0; nt < 4; nt++) {
                    const uint32_t* bH = (const uint32_t*)s->bHi[buf][n0w + nt * 8 + gid];
                    const uint32_t* bL = (const uint32_t*)s->bLo[buf][n0w + nt * 8 + gid];
                    uint32_t bh[2] = { bH[w], bH[w + 4] };
                    uint32_t bl[2] = { bL[w], bL[w + 4] };
                    mma_bf16(acc[mt][nt], ah, bh);
                    mma_bf16(acc[mt][nt], ah, bl);
                    mma_bf16(acc[mt][nt], al, bh);
                }
            }
        }
        __syncthreads();
    }

#pragma unroll
    for (int mt = 0; mt < 4; mt++)
#pragma unroll
        for (int nt = 0; nt < 4; nt++)
#pragma unroll
            for (int j = 0; j < 4; j++) {
                const int r = rowA + m0w + mt * 16 + gid + ((j >> 1) << 3);
                const int c = rowB + n0w + nt * 8 + 2 * tid4 + (j & 1);
                C[(size_t)r * N + c] = acc[mt][nt][j] + bias[c];
            }
}

// ======================= packing kernels ====================================
__global__ __launch_bounds__(256) void split_rows(const float* __restrict__ src,
        bf16* __restrict__ hi, bf16* __restrict__ lo, size_t n) {
    for (size_t i = (size_t)blockIdx.x * blockDim.x + threadIdx.x;
         i < n; i += (size_t)gridDim.x * blockDim.x) {
        const float v = src[i];
        const bf16 h = __float2bfloat16(v);
        hi[i] = h;
        lo[i] = __float2bfloat16(v - __bfloat162float(h));
    }
}

__global__ __launch_bounds__(256) void split_transpose(const float* __restrict__ src,
        bf16* __restrict__ hi, bf16* __restrict__ lo, int K, int N) {
    const size_t total = (size_t)K * N;
    for (size_t i = (size_t)blockIdx.x * blockDim.x + threadIdx.x;
         i < total; i += (size_t)gridDim.x * blockDim.x) {
        const int n = (int)(i / K);
        const int k = (int)(i % K);
        const float v = src[(size_t)k * N + n];
        const bf16 h = __float2bfloat16(v);
        hi[i] = h;
        lo[i] = __float2bfloat16(v - __bfloat162float(h));
    }
}

__global__ __launch_bounds__(256) void pack_w_bf16(const float* __restrict__ W,
                                                   bf16* __restrict__ P) {
    const size_t total = (size_t)NCTA * 32 * HID;
    for (size_t idx = (size_t)blockIdx.x * blockDim.x + threadIdx.x;
         idx < total; idx += (size_t)gridDim.x * blockDim.x) {
        const int cta = (int)(idx >> 15);
        const int n   = (int)((idx >> 10) & 31);
        const int k   = (int)(idx & 1023);
        const int gcol = (n >> 3) * HID + cta * 8 + (n & 7);
        const float w = W[(size_t)k * G4 + gcol];
        const bf16 hi = __float2bfloat16(w);
        const bf16 lo = __float2bfloat16(w - __bfloat162float(hi));
        const size_t base = (size_t)cta * 2 * 32 * HID;
        P[base + (size_t)n * HID + k] = hi;
        P[base + (size_t)32 * HID + (size_t)n * HID + k] = lo;
    }
}

// ---------------- launch ----------------------------------------------------
extern "C" void kernel_launch(void* const* d_in, const int* in_sizes, int n_in,
                              void* d_out, int out_size) {
    const float* inputs = (const float*)d_in[0];
    const float* Wx0    = (const float*)d_in[1];
    const float* Wh0    = (const float*)d_in[2];
    const float* b0     = (const float*)d_in[3];
    const float* Wx1    = (const float*)d_in[4];
    const float* Wh1    = (const float*)d_in[5];
    const float* b1     = (const float*)d_in[6];
    const float* Wout   = (const float*)d_in[7];
    const float* bout   = (const float*)d_in[8];
    float* out = (float*)d_out;

    float *pGX;
    bf16 *pp0, *pp1, *pp2, *pinH, *pinL, *pWx0h, *pWx0l, *pWoh, *pWol, *pH1h, *pH1l;
    cudaGetSymbolAddress((void**)&pGX,   g_GX);
    cudaGetSymbolAddress((void**)&pp0,   g_pWh0);
    cudaGetSymbolAddress((void**)&pp1,   g_pWx1);
    cudaGetSymbolAddress((void**)&pp2,   g_pWh1);
    cudaGetSymbolAddress((void**)&pinH,  g_inHi);
    cudaGetSymbolAddress((void**)&pinL,  g_inLo);
    cudaGetSymbolAddress((void**)&pWx0h, g_Wx0Thi);
    cudaGetSymbolAddress((void**)&pWx0l, g_Wx0Tlo);
    cudaGetSymbolAddress((void**)&pWoh,  g_WoutThi);
    cudaGetSymbolAddress((void**)&pWol,  g_WoutTlo);
    cudaGetSymbolAddress((void**)&pH1h,  g_H1hi);
    cudaGetSymbolAddress((void**)&pH1l,  g_H1lo);

    cudaFuncSetAttribute(lstm_fused, cudaFuncAttributeMaxDynamicSharedMemorySize,
                         (int)sizeof(SmemT));
    cudaFuncSetAttribute(gemm_mma_big, cudaFuncAttributeMaxDynamicSharedMemorySize,
                         (int)sizeof(GSmem));

    // 0) packing / splitting
    pack_w_bf16<<<1024, 256>>>(Wh0, pp0);
    pack_w_bf16<<<1024, 256>>>(Wx1, pp1);
    pack_w_bf16<<<1024, 256>>>(Wh1, pp2);
    split_rows<<<2048, 256>>>(inputs, pinH, pinL, (size_t)MB * DIN);
    split_transpose<<<1024, 256>>>(Wx0, pWx0h, pWx0l, DIN, G4);
    split_transpose<<<512, 256>>>(Wout, pWoh, pWol, HID, DOUT);

    // 1) GX = inputs @ Wx0 + b0   (tensor cores)
    gemm_mma_big<<<dim3(G4 / 128, MB / 128), 256, sizeof(GSmem)>>>(
        pinH, pinL, pWx0h, pWx0l, b0, pGX, MB, G4, DIN);

    // 2) fused 256-step recurrence (one hidden barrier per step)
    lstm_fused<<<NCTA, 256, sizeof(SmemT)>>>(b1, out);

    // 3) outs = H1_all @ Wout + bout  (tensor cores)
    gemm_mma_big<<<dim3(DOUT / 128, MB / 128), 256, sizeof(GSmem)>>>(
        pH1h, pH1l, pWoh, pWol, bout, out, MB, DOUT, HID);
}